// round 2
// baseline (speedup 1.0000x reference)
#include <cuda_runtime.h>
#include <math.h>

// Problem constants
#define BB 2
#define TT 2048
#define DD 1024
#define HH 16
#define DH 64
#define MM (BB*TT)   // 4096 rows

// ---------------- scratch (device globals; no allocation allowed) ----------------
#define OFF_Y    0u
#define OFF_Q    4194304u
#define OFF_K    8388608u
#define OFF_V    12582912u
#define OFF_O    16777216u
#define OFF_X1   20971520u
#define OFF_Y3   25165824u
#define OFF_H4   29360128u   // 4096 x 4096
#define OFF_YG   46137344u   // 4096 x 2048
#define OFF_MWQ  54525952u
#define OFF_MWV  55574528u
#define OFF_MWFC 56623104u
#define OFF_MW1  57671680u   // 4096 x 1024
#define OFF_MW2  61865984u   // 1024 x 2048
#define SCRATCH_TOTAL 63963136u

__device__ float g_scratch[SCRATCH_TOTAL];
__device__ int   g_btab[4095];

// ---------------- T5 relative bucket table ----------------
__global__ void bucket_kernel(int* btab) {
    int idx = blockIdx.x * 256 + threadIdx.x;
    if (idx >= 4095) return;
    int rel = idx - 2047;              // key_pos - query_pos
    int b = (rel > 0) ? 16 : 0;
    int a = rel < 0 ? -rel : rel;
    if (a < 8) {
        b += a;
    } else {
        int large;
        if ((a & (a - 1)) == 0) {      // exact power of two: integer-exact path
            int e = 31 - __clz(a);
            large = 8 + 2 * (e - 3);
        } else {
            large = 8 + (int)(2.0 * (log2((double)a) - 3.0));
        }
        b += (large < 15) ? large : 15;
    }
    btab[idx] = b;
}

// ---------------- pos_bias output: [H, T, T] ----------------
__global__ void posbias_kernel(const float* __restrict__ relb,
                               const int* __restrict__ btab,
                               float* __restrict__ out) {
    int idx = blockIdx.x * 256 + threadIdx.x;    // < 16*2048*2048 = 67108864
    if (idx >= HH * TT * TT) return;
    int h = idx >> 22;
    int r = idx & 4194303;
    int i = r >> 11;
    int j = r & 2047;
    out[idx] = relb[btab[j - i + 2047] * HH + h];
}

// ---------------- LoRA weight merge: out = W + 0.125 * Bm @ A ----------------
__global__ void merge_kernel(const float* __restrict__ W,
                             const float* __restrict__ A,
                             const float* __restrict__ Bm,
                             float* __restrict__ out, int N, int K) {
    int idx = blockIdx.x * 256 + threadIdx.x;
    if (idx >= N * K) return;
    int n = idx / K, kk = idx - n * K;
    float s = 0.f;
#pragma unroll
    for (int r = 0; r < 8; r++) s += Bm[n * 8 + r] * A[r * K + kk];
    out[idx] = W[idx] + 0.125f * s;
}

// ---------------- RMSNorm (row-wise over D=1024) ----------------
__global__ void rmsnorm_kernel(const float* __restrict__ x,
                               const float* __restrict__ w,
                               float* __restrict__ y) {
    int row = blockIdx.x;
    const float* xp = x + (size_t)row * DD;
    float ss = 0.f;
    for (int d = threadIdx.x; d < DD; d += 256) { float v = xp[d]; ss += v * v; }
    __shared__ float red[256];
    red[threadIdx.x] = ss;
    __syncthreads();
    for (int s = 128; s > 0; s >>= 1) {
        if (threadIdx.x < s) red[threadIdx.x] += red[threadIdx.x + s];
        __syncthreads();
    }
    float inv = rsqrtf(red[0] * (1.0f / DD) + 1e-6f);
    float* yp = y + (size_t)row * DD;
    for (int d = threadIdx.x; d < DD; d += 256) yp[d] = w[d] * xp[d] * inv;
}

// ---------------- SGEMM: C[M,N] = A[M,K] @ W[N,K]^T (+ res) ----------------
// 128x128 tile, BK=8, 256 threads, 8x8 microtile.
__global__ void __launch_bounds__(256) gemm_nt_kernel(
    const float* __restrict__ A, const float* __restrict__ W,
    const float* __restrict__ res, float* __restrict__ C,
    int M, int N, int K)
{
    __shared__ float As[8][132];
    __shared__ float Ws[8][132];
    int tid = threadIdx.x;
    int lrow = tid >> 1;            // 0..127
    int lcol = (tid & 1) << 2;      // 0 or 4
    int bm = blockIdx.y * 128, bn = blockIdx.x * 128;
    const float* Ap = A + (size_t)(bm + lrow) * K + lcol;
    const float* Wp = W + (size_t)(bn + lrow) * K + lcol;
    int tx = tid & 15, ty = tid >> 4;
    float acc[8][8];
#pragma unroll
    for (int i = 0; i < 8; i++)
#pragma unroll
        for (int j = 0; j < 8; j++) acc[i][j] = 0.f;

    for (int k0 = 0; k0 < K; k0 += 8) {
        float4 a4 = *(const float4*)(Ap + k0);
        float4 w4 = *(const float4*)(Wp + k0);
        As[lcol + 0][lrow] = a4.x; As[lcol + 1][lrow] = a4.y;
        As[lcol + 2][lrow] = a4.z; As[lcol + 3][lrow] = a4.w;
        Ws[lcol + 0][lrow] = w4.x; Ws[lcol + 1][lrow] = w4.y;
        Ws[lcol + 2][lrow] = w4.z; Ws[lcol + 3][lrow] = w4.w;
        __syncthreads();
#pragma unroll
        for (int kk = 0; kk < 8; kk++) {
            float ra[8], rb[8];
            *(float4*)(ra)     = *(float4*)&As[kk][ty * 8];
            *(float4*)(ra + 4) = *(float4*)&As[kk][ty * 8 + 4];
            *(float4*)(rb)     = *(float4*)&Ws[kk][tx * 8];
            *(float4*)(rb + 4) = *(float4*)&Ws[kk][tx * 8 + 4];
#pragma unroll
            for (int i = 0; i < 8; i++)
#pragma unroll
                for (int j = 0; j < 8; j++) acc[i][j] += ra[i] * rb[j];
        }
        __syncthreads();
    }
#pragma unroll
    for (int i = 0; i < 8; i++) {
        size_t crow = (size_t)(bm + ty * 8 + i);
        float* Cp = C + crow * N + bn + tx * 8;
        if (res) {
            const float* Rp = res + crow * N + bn + tx * 8;
            float4 r0 = *(const float4*)(Rp);
            float4 r1 = *(const float4*)(Rp + 4);
            float4 o0 = make_float4(acc[i][0] + r0.x, acc[i][1] + r0.y,
                                    acc[i][2] + r0.z, acc[i][3] + r0.w);
            float4 o1 = make_float4(acc[i][4] + r1.x, acc[i][5] + r1.y,
                                    acc[i][6] + r1.z, acc[i][7] + r1.w);
            *(float4*)(Cp) = o0;
            *(float4*)(Cp + 4) = o1;
        } else {
            float4 o0 = make_float4(acc[i][0], acc[i][1], acc[i][2], acc[i][3]);
            float4 o1 = make_float4(acc[i][4], acc[i][5], acc[i][6], acc[i][7]);
            *(float4*)(Cp) = o0;
            *(float4*)(Cp + 4) = o1;
        }
    }
}

// ---------------- Flash attention with T5 bias + mask ----------------
#define AST 68
#define ATT_SMEM ((4 * 64 * AST + 32) * 4)

__global__ void __launch_bounds__(256) attn_kernel(
    const float* __restrict__ q, const float* __restrict__ k,
    const float* __restrict__ v, const int* __restrict__ xmask,
    const float* __restrict__ relb, const int* __restrict__ btab,
    float* __restrict__ o)
{
    extern __shared__ float sm[];
    float* Qs = sm;
    float* Ks = Qs + 64 * AST;
    float* Vs = Ks + 64 * AST;
    float* Ss = Vs + 64 * AST;
    float* sBias = Ss + 64 * AST;   // 32 floats

    int qt = blockIdx.x, h = blockIdx.y, b = blockIdx.z;
    int tid = threadIdx.x;
    int tx = tid & 15, ty = tid >> 4;
    int r0 = ty << 2, c0 = tx << 2;
    int i0 = qt << 6;

    if (tid < 32) sBias[tid] = relb[tid * HH + h];

    const size_t base = (size_t)b * TT * DD + h * DH;

    // load+scale Q tile [64 x 64]
    for (int t = tid; t < 64 * 16; t += 256) {
        int rr = t >> 4, cc = (t & 15) << 2;
        float4 qv = *(const float4*)(q + base + (size_t)(i0 + rr) * DD + cc);
        Qs[rr * AST + cc + 0] = qv.x * 0.125f;
        Qs[rr * AST + cc + 1] = qv.y * 0.125f;
        Qs[rr * AST + cc + 2] = qv.z * 0.125f;
        Qs[rr * AST + cc + 3] = qv.w * 0.125f;
    }

    float acc[4][4];
#pragma unroll
    for (int i = 0; i < 4; i++)
#pragma unroll
        for (int j = 0; j < 4; j++) acc[i][j] = 0.f;
    float mprev[4] = {-1e30f, -1e30f, -1e30f, -1e30f};
    float lprev[4] = {0.f, 0.f, 0.f, 0.f};
    __syncthreads();

    for (int kt = 0; kt < TT / 64; kt++) {
        int j0 = kt << 6;
        for (int t = tid; t < 64 * 16; t += 256) {
            int rr = t >> 4, cc = (t & 15) << 2;
            *(float4*)&Ks[rr * AST + cc] = *(const float4*)(k + base + (size_t)(j0 + rr) * DD + cc);
            *(float4*)&Vs[rr * AST + cc] = *(const float4*)(v + base + (size_t)(j0 + rr) * DD + cc);
        }
        __syncthreads();

        // S = (0.125*Q) K^T
        float s[4][4];
#pragma unroll
        for (int i = 0; i < 4; i++)
#pragma unroll
            for (int j = 0; j < 4; j++) s[i][j] = 0.f;
#pragma unroll
        for (int d = 0; d < 64; d += 4) {
            float4 qa[4], kb[4];
#pragma unroll
            for (int i = 0; i < 4; i++) qa[i] = *(float4*)&Qs[(r0 + i) * AST + d];
#pragma unroll
            for (int j = 0; j < 4; j++) kb[j] = *(float4*)&Ks[(c0 + j) * AST + d];
#pragma unroll
            for (int i = 0; i < 4; i++)
#pragma unroll
                for (int j = 0; j < 4; j++)
                    s[i][j] += qa[i].x * kb[j].x + qa[i].y * kb[j].y
                             + qa[i].z * kb[j].z + qa[i].w * kb[j].w;
        }
        // bias + mask
#pragma unroll
        for (int i = 0; i < 4; i++) {
            int gi = i0 + r0 + i;
            const int* mrow = xmask + ((size_t)b * TT + gi) * TT + j0 + c0;
#pragma unroll
            for (int j = 0; j < 4; j++) {
                int gj = j0 + c0 + j;
                float bias = sBias[btab[gj - gi + 2047]];
                s[i][j] = (mrow[j] != 0) ? (s[i][j] + bias) : -1e9f;
            }
        }
        // online softmax (row group = 16 lanes sharing ty)
#pragma unroll
        for (int i = 0; i < 4; i++) {
            float m = fmaxf(fmaxf(s[i][0], s[i][1]), fmaxf(s[i][2], s[i][3]));
            m = fmaxf(m, __shfl_xor_sync(0xffffffffu, m, 8, 16));
            m = fmaxf(m, __shfl_xor_sync(0xffffffffu, m, 4, 16));
            m = fmaxf(m, __shfl_xor_sync(0xffffffffu, m, 2, 16));
            m = fmaxf(m, __shfl_xor_sync(0xffffffffu, m, 1, 16));
            float mnew = fmaxf(mprev[i], m);
            float corr = __expf(mprev[i] - mnew);
            float ps = 0.f;
#pragma unroll
            for (int j = 0; j < 4; j++) { s[i][j] = __expf(s[i][j] - mnew); ps += s[i][j]; }
            ps += __shfl_xor_sync(0xffffffffu, ps, 8, 16);
            ps += __shfl_xor_sync(0xffffffffu, ps, 4, 16);
            ps += __shfl_xor_sync(0xffffffffu, ps, 2, 16);
            ps += __shfl_xor_sync(0xffffffffu, ps, 1, 16);
            lprev[i] = lprev[i] * corr + ps;
            mprev[i] = mnew;
#pragma unroll
            for (int j = 0; j < 4; j++) acc[i][j] *= corr;
#pragma unroll
            for (int j = 0; j < 4; j++) Ss[(r0 + i) * AST + c0 + j] = s[i][j];
        }
        __syncthreads();
        // O += P @ V   (thread owns rows r0..r0+3, head-dims c0..c0+3)
#pragma unroll 8
        for (int c = 0; c < 64; c++) {
            float4 vv = *(float4*)&Vs[c * AST + c0];
#pragma unroll
            for (int i = 0; i < 4; i++) {
                float p = Ss[(r0 + i) * AST + c];
                acc[i][0] += p * vv.x;
                acc[i][1] += p * vv.y;
                acc[i][2] += p * vv.z;
                acc[i][3] += p * vv.w;
            }
        }
        __syncthreads();
    }
#pragma unroll
    for (int i = 0; i < 4; i++) {
        float invl = 1.f / lprev[i];
        float4 ov = make_float4(acc[i][0] * invl, acc[i][1] * invl,
                                acc[i][2] * invl, acc[i][3] * invl);
        *(float4*)(o + base + (size_t)(i0 + r0 + i) * DD + c0) = ov;
    }
}

// ---------------- GEGLU: yg = p1 * gelu_tanh(p2) ----------------
__global__ void geglu_kernel(const float* __restrict__ h, float* __restrict__ yg) {
    int idx = blockIdx.x * 256 + threadIdx.x;   // < 4096*2048
    if (idx >= MM * 2048) return;
    int m = idx >> 11, c = idx & 2047;
    float p1 = h[(size_t)m * 4096 + c];
    float p2 = h[(size_t)m * 4096 + 2048 + c];
    float u = 0.7978845608f * (p2 + 0.044715f * p2 * p2 * p2);
    float g = 0.5f * p2 * (1.f + tanhf(u));
    yg[idx] = p1 * g;
}

// ---------------- launch ----------------
extern "C" void kernel_launch(void* const* d_in, const int* in_sizes, int n_in,
                              void* d_out, int out_size) {
    const float* x     = (const float*)d_in[0];
    const int*   xmask = (const int*)d_in[1];
    // d_in[2] = cond (unused, FiLM identity)
    const float* n1w   = (const float*)d_in[3];
    const float* n3w   = (const float*)d_in[4];
    const float* wqW   = (const float*)d_in[5];
    const float* wqA   = (const float*)d_in[6];
    const float* wqB   = (const float*)d_in[7];
    const float* wkW   = (const float*)d_in[8];
    const float* wvW   = (const float*)d_in[9];
    const float* wvA   = (const float*)d_in[10];
    const float* wvB   = (const float*)d_in[11];
    const float* fcW   = (const float*)d_in[12];
    const float* fcA   = (const float*)d_in[13];
    const float* fcB   = (const float*)d_in[14];
    const float* relb  = (const float*)d_in[15];
    const float* w1W   = (const float*)d_in[16];
    const float* w1A   = (const float*)d_in[17];
    const float* w1B   = (const float*)d_in[18];
    const float* w2W   = (const float*)d_in[19];
    const float* w2A   = (const float*)d_in[20];
    const float* w2B   = (const float*)d_in[21];

    float* scratch = nullptr;
    int*   btab    = nullptr;
    cudaGetSymbolAddress((void**)&scratch, g_scratch);
    cudaGetSymbolAddress((void**)&btab, g_btab);

    float* y   = scratch + OFF_Y;
    float* q   = scratch + OFF_Q;
    float* k   = scratch + OFF_K;
    float* v   = scratch + OFF_V;
    float* o   = scratch + OFF_O;
    float* x1  = scratch + OFF_X1;
    float* y3  = scratch + OFF_Y3;
    float* h4  = scratch + OFF_H4;
    float* yg  = scratch + OFF_YG;
    float* mWq = scratch + OFF_MWQ;
    float* mWv = scratch + OFF_MWV;
    float* mWfc= scratch + OFF_MWFC;
    float* mW1 = scratch + OFF_MW1;
    float* mW2 = scratch + OFF_MW2;

    float* out_x    = (float*)d_out;
    float* out_bias = out_x + (size_t)MM * DD;   // 4194304

    cudaFuncSetAttribute(attn_kernel, cudaFuncAttributeMaxDynamicSharedMemorySize, ATT_SMEM);

    // 1) bucket table + pos_bias output
    bucket_kernel<<<(4095 + 255) / 256, 256>>>(btab);
    posbias_kernel<<<(HH * TT * TT) / 256, 256>>>(relb, btab, out_bias);

    // 2) merge LoRA weights
    merge_kernel<<<(DD * DD) / 256, 256>>>(wqW, wqA, wqB, mWq, DD, DD);
    merge_kernel<<<(DD * DD) / 256, 256>>>(wvW, wvA, wvB, mWv, DD, DD);
    merge_kernel<<<(DD * DD) / 256, 256>>>(fcW, fcA, fcB, mWfc, DD, DD);
    merge_kernel<<<(4 * DD * DD) / 256, 256>>>(w1W, w1A, w1B, mW1, 4 * DD, DD);
    merge_kernel<<<(2 * DD * DD) / 256, 256>>>(w2W, w2A, w2B, mW2, DD, 2 * DD);

    // 3) attention block
    rmsnorm_kernel<<<MM, 256>>>(x, n1w, y);
    {
        dim3 g(DD / 128, MM / 128);
        gemm_nt_kernel<<<g, 256>>>(y, mWq, nullptr, q, MM, DD, DD);
        gemm_nt_kernel<<<g, 256>>>(y, wkW, nullptr, k, MM, DD, DD);
        gemm_nt_kernel<<<g, 256>>>(y, mWv, nullptr, v, MM, DD, DD);
    }
    {
        dim3 g(TT / 64, HH, BB);
        attn_kernel<<<g, 256, ATT_SMEM>>>(q, k, v, xmask, relb, btab, o);
    }
    {
        dim3 g(DD / 128, MM / 128);
        gemm_nt_kernel<<<g, 256>>>(o, mWfc, x, x1, MM, DD, DD);   // x1 = x + fc(o)
    }

    // 4) GEGLU MLP
    rmsnorm_kernel<<<MM, 256>>>(x1, n3w, y3);
    {
        dim3 g(4 * DD / 128, MM / 128);
        gemm_nt_kernel<<<g, 256>>>(y3, mW1, nullptr, h4, MM, 4 * DD, DD);
    }
    geglu_kernel<<<(MM * 2048) / 256, 256>>>(h4, yg);
    {
        dim3 g(DD / 128, MM / 128);
        gemm_nt_kernel<<<g, 256>>>(yg, mW2, x1, out_x, MM, DD, 2 * DD);  // out = x1 + w2(yg)
    }
}

// round 9
// speedup vs baseline: 1.4675x; 1.4675x over previous
#include <cuda_runtime.h>
#include <cuda_bf16.h>
#include <math.h>
#include <stdint.h>

// Problem constants
#define BB 2
#define TT 2048
#define DD 1024
#define HH 16
#define DH 64
#define MM (BB*TT)   // 4096 rows

// ---------------- scratch layout (floats) ----------------
#define OFF_Q     0u
#define OFF_K     4194304u
#define OFF_V     8388608u
#define OFF_O     12582912u
#define OFF_X1    16777216u
#define OFF_H4    20971520u   // 4096 x 4096 f32
#define OFF_YHL   37748736u   // bf16 [8192,1024]
#define OFF_OHL   41943040u
#define OFF_Y3HL  46137344u
#define OFF_YGHL  50331648u   // bf16 [8192,2048]
#define OFF_WQHL  58720256u   // bf16 [2048,1024]
#define OFF_WKHL  59768832u
#define OFF_WVHL  60817408u
#define OFF_WFCHL 61865984u
#define OFF_W1HL  62914560u   // bf16 [8192,1024]
#define OFF_W2HL  67108864u   // bf16 [2048,2048]
#define SCRATCH_TOTAL 69206016u

__device__ float g_scratch[SCRATCH_TOTAL];
__device__ int   g_btab[4095];

// ================= portable PTX helpers (sm_80-era base ISA only) =================
__device__ __forceinline__ uint32_t smem_u32(const void* p) {
    uint32_t a;
    asm("{ .reg .u64 t; cvta.to.shared.u64 t, %1; cvt.u32.u64 %0, t; }"
        : "=r"(a) : "l"(p));
    return a;
}

#define CP_ASYNC16(s, g) \
    asm volatile("cp.async.cg.shared.global [%0], [%1], 16;" :: "r"(s), "l"(g))
#define CP_COMMIT() asm volatile("cp.async.commit_group;")
#define CP_WAIT(n)  asm volatile("cp.async.wait_group %0;" :: "n"(n))

__device__ __forceinline__ void ldsm_x4(uint32_t* d, uint32_t a) {
    asm volatile("ldmatrix.sync.aligned.m8n8.x4.shared.b16 {%0,%1,%2,%3}, [%4];"
        : "=r"(d[0]), "=r"(d[1]), "=r"(d[2]), "=r"(d[3]) : "r"(a));
}

__device__ __forceinline__ void mma_bf16(float* c, const uint32_t* a,
                                         uint32_t b0, uint32_t b1) {
    asm volatile(
        "mma.sync.aligned.m16n8k16.row.col.f32.bf16.bf16.f32 "
        "{%0,%1,%2,%3}, {%4,%5,%6,%7}, {%8,%9}, {%0,%1,%2,%3};"
        : "+f"(c[0]), "+f"(c[1]), "+f"(c[2]), "+f"(c[3])
        : "r"(a[0]), "r"(a[1]), "r"(a[2]), "r"(a[3]), "r"(b0), "r"(b1));
}

// ---------------- T5 relative bucket table ----------------
__global__ void bucket_kernel(int* btab) {
    int idx = blockIdx.x * 256 + threadIdx.x;
    if (idx >= 4095) return;
    int rel = idx - 2047;
    int b = (rel > 0) ? 16 : 0;
    int a = rel < 0 ? -rel : rel;
    if (a < 8) {
        b += a;
    } else {
        int large;
        if ((a & (a - 1)) == 0) {
            int e = 31 - __clz(a);
            large = 8 + 2 * (e - 3);
        } else {
            large = 8 + (int)(2.0 * (log2((double)a) - 3.0));
        }
        b += (large < 15) ? large : 15;
    }
    btab[idx] = b;
}

// ---------------- pos_bias output: [H, T, T] ----------------
__global__ void posbias_kernel(const float* __restrict__ relb,
                               const int* __restrict__ btab,
                               float* __restrict__ out) {
    int idx = blockIdx.x * 256 + threadIdx.x;
    if (idx >= HH * TT * TT) return;
    int h = idx >> 22;
    int r = idx & 4194303;
    int i = r >> 11;
    int j = r & 2047;
    out[idx] = relb[btab[j - i + 2047] * HH + h];
}

// ---------------- LoRA merge -> bf16 hi/lo ----------------
__global__ void merge_hl_kernel(const float* __restrict__ W,
                                const float* __restrict__ A,
                                const float* __restrict__ Bm,
                                __nv_bfloat16* __restrict__ out, int N, int K) {
    int idx = blockIdx.x * 256 + threadIdx.x;
    if (idx >= N * K) return;
    int n = idx / K, kk = idx - n * K;
    float s = 0.f;
#pragma unroll
    for (int r = 0; r < 8; r++) s += Bm[n * 8 + r] * A[r * K + kk];
    float m = W[idx] + 0.125f * s;
    __nv_bfloat16 hi = __float2bfloat16(m);
    out[(size_t)n * K + kk] = hi;
    out[(size_t)(N + n) * K + kk] = __float2bfloat16(m - __bfloat162float(hi));
}

// ---------------- f32 -> bf16 hi/lo ----------------
__global__ void convert_hl_kernel(const float* __restrict__ in,
                                  __nv_bfloat16* __restrict__ out, int rows, int cols) {
    int idx = blockIdx.x * 256 + threadIdx.x;
    if (idx >= rows * cols) return;
    int r = idx / cols, c = idx - r * cols;
    float v = in[idx];
    __nv_bfloat16 hi = __float2bfloat16(v);
    out[(size_t)r * cols + c] = hi;
    out[(size_t)(rows + r) * cols + c] = __float2bfloat16(v - __bfloat162float(hi));
}

// ---------------- RMSNorm -> bf16 hi/lo ----------------
__global__ void rmsnorm_hl_kernel(const float* __restrict__ x,
                                  const float* __restrict__ w,
                                  __nv_bfloat16* __restrict__ yhl) {
    int row = blockIdx.x;
    const float* xp = x + (size_t)row * DD;
    float ss = 0.f;
    for (int d = threadIdx.x; d < DD; d += 256) { float v = xp[d]; ss += v * v; }
    __shared__ float red[256];
    red[threadIdx.x] = ss;
    __syncthreads();
    for (int s = 128; s > 0; s >>= 1) {
        if (threadIdx.x < s) red[threadIdx.x] += red[threadIdx.x + s];
        __syncthreads();
    }
    float inv = rsqrtf(red[0] * (1.0f / DD) + 1e-6f);
    for (int d = threadIdx.x; d < DD; d += 256) {
        float v = w[d] * xp[d] * inv;
        __nv_bfloat16 hi = __float2bfloat16(v);
        yhl[(size_t)row * DD + d] = hi;
        yhl[(size_t)(MM + row) * DD + d] = __float2bfloat16(v - __bfloat162float(hi));
    }
}

// ---------------- GEGLU -> bf16 hi/lo ----------------
__global__ void geglu_hl_kernel(const float* __restrict__ h,
                                __nv_bfloat16* __restrict__ yghl) {
    int idx = blockIdx.x * 256 + threadIdx.x;
    if (idx >= MM * 2048) return;
    int m = idx >> 11, c = idx & 2047;
    float p1 = h[(size_t)m * 4096 + c];
    float p2 = h[(size_t)m * 4096 + 2048 + c];
    float u = 0.7978845608f * (p2 + 0.044715f * p2 * p2 * p2);
    float g = 0.5f * p2 * (1.f + tanhf(u));
    float v = p1 * g;
    __nv_bfloat16 hi = __float2bfloat16(v);
    yghl[(size_t)m * 2048 + c] = hi;
    yghl[(size_t)(MM + m) * 2048 + c] = __float2bfloat16(v - __bfloat162float(hi));
}

// ================= mma.sync bf16 hi/lo GEMM =================
// C[M,N] = (Ahi+Alo)[M,K] @ (Whi+Wlo)[N,K]^T (+res)
// Tile 128x128, BK=32, 256 threads = 8 warps (4 M x 2 N), warp tile 32x64.
// 3 mma passes per tile: Ah*Wh + Ah*Wl + Al*Wh (Al*Wl term negligible).
#define GP      40                // padded smem stride in halves (80 B rows)
#define GBUF    (128 * GP * 2)    // 10240 B per operand buffer
#define GSTAGE  (4 * GBUF)        // Ahi, Alo, Whi, Wlo
#define GEMM_SMEM (2 * GSTAGE)    // double buffered: 81920 B

__device__ __forceinline__ void load_chunk_mma(
    const char* Ab, const char* Wb, int K, int Mtot, int Ntot,
    int bm, int bn, int k0, uint32_t sstage, int tid)
{
    size_t pitch = (size_t)K * 2;
    size_t kb = (size_t)k0 * 2;
#pragma unroll
    for (int i = 0; i < 8; i++) {
        int idx = tid + 256 * i;        // 0..2047
        int buf = idx >> 9;             // 0:Ahi 1:Alo 2:Whi 3:Wlo
        int rem = idx & 511;
        int r = rem >> 2, cg = rem & 3; // row 0..127, 16B col group 0..3
        const char* src;
        if (buf == 0)      src = Ab + (size_t)(bm + r) * pitch + kb + cg * 16;
        else if (buf == 1) src = Ab + (size_t)(Mtot + bm + r) * pitch + kb + cg * 16;
        else if (buf == 2) src = Wb + (size_t)(bn + r) * pitch + kb + cg * 16;
        else               src = Wb + (size_t)(Ntot + bn + r) * pitch + kb + cg * 16;
        CP_ASYNC16(sstage + (uint32_t)(buf * GBUF + r * (GP * 2) + cg * 16), src);
    }
}

__global__ void __launch_bounds__(256, 1) gemm_mma_kernel(
    const __nv_bfloat16* __restrict__ Ahl, const __nv_bfloat16* __restrict__ Whl,
    const float* __restrict__ res, float* __restrict__ C,
    int Mtot, int Ntot, int K)
{
    extern __shared__ char gsm[];
    uint32_t sb = smem_u32(gsm);
    int tid = threadIdx.x;
    int lane = tid & 31, w = tid >> 5;
    int wm = (w & 3) * 32, wn = (w >> 2) * 64;
    int bm = blockIdx.y * 128, bn = blockIdx.x * 128;
    const char* Ab = (const char*)Ahl;
    const char* Wb = (const char*)Whl;

    float acc[2][8][4];
#pragma unroll
    for (int mt = 0; mt < 2; mt++)
#pragma unroll
        for (int nt = 0; nt < 8; nt++)
#pragma unroll
            for (int e = 0; e < 4; e++) acc[mt][nt][e] = 0.f;

    int nc = K / 32;
    load_chunk_mma(Ab, Wb, K, Mtot, Ntot, bm, bn, 0, sb, tid);
    CP_COMMIT();

    for (int c = 0; c < nc; c++) {
        int s = c & 1;
        if (c + 1 < nc) {
            load_chunk_mma(Ab, Wb, K, Mtot, Ntot, bm, bn, (c + 1) * 32,
                           sb + (uint32_t)((s ^ 1) * GSTAGE), tid);
            CP_COMMIT();
            CP_WAIT(1);
        } else {
            CP_WAIT(0);
        }
        __syncthreads();
        uint32_t st = sb + (uint32_t)(s * GSTAGE);
#pragma unroll
        for (int ks = 0; ks < 2; ks++) {
            int k0 = ks * 16;
            uint32_t ah[2][4], al[2][4], bh[4][4], bl[4][4];
#pragma unroll
            for (int mt = 0; mt < 2; mt++) {
                uint32_t row = (uint32_t)(wm + mt * 16 + (lane & 15));
                uint32_t col = (uint32_t)(k0 + ((lane >> 4) << 3));
                uint32_t off = row * (GP * 2) + col * 2;
                ldsm_x4(ah[mt], st + off);
                ldsm_x4(al[mt], st + GBUF + off);
            }
#pragma unroll
            for (int g = 0; g < 4; g++) {
                uint32_t grp = (uint32_t)(lane >> 3);
                uint32_t row = (uint32_t)(wn + g * 16) + ((grp >> 1) << 3) + (uint32_t)(lane & 7);
                uint32_t col = (uint32_t)k0 + ((grp & 1) << 3);
                uint32_t off = row * (GP * 2) + col * 2;
                ldsm_x4(bh[g], st + 2 * GBUF + off);
                ldsm_x4(bl[g], st + 3 * GBUF + off);
            }
#pragma unroll
            for (int mt = 0; mt < 2; mt++)
#pragma unroll
                for (int nt = 0; nt < 8; nt++) {
                    uint32_t b0h = bh[nt >> 1][(nt & 1) * 2];
                    uint32_t b1h = bh[nt >> 1][(nt & 1) * 2 + 1];
                    uint32_t b0l = bl[nt >> 1][(nt & 1) * 2];
                    uint32_t b1l = bl[nt >> 1][(nt & 1) * 2 + 1];
                    mma_bf16(acc[mt][nt], ah[mt], b0h, b1h);
                    mma_bf16(acc[mt][nt], ah[mt], b0l, b1l);
                    mma_bf16(acc[mt][nt], al[mt], b0h, b1h);
                }
        }
        __syncthreads();
    }

    // epilogue: registers -> gmem (optional residual add)
#pragma unroll
    for (int mt = 0; mt < 2; mt++)
#pragma unroll
        for (int nt = 0; nt < 8; nt++) {
            int m0 = bm + wm + mt * 16 + (lane >> 2);
            int n  = bn + wn + nt * 8 + ((lane & 3) << 1);
            size_t i0 = (size_t)m0 * Ntot + n;
            size_t i1 = (size_t)(m0 + 8) * Ntot + n;
            float2 v0 = make_float2(acc[mt][nt][0], acc[mt][nt][1]);
            float2 v1 = make_float2(acc[mt][nt][2], acc[mt][nt][3]);
            if (res) {
                float2 r0 = *(const float2*)(res + i0);
                float2 r1 = *(const float2*)(res + i1);
                v0.x += r0.x; v0.y += r0.y;
                v1.x += r1.x; v1.y += r1.y;
            }
            *(float2*)(C + i0) = v0;
            *(float2*)(C + i1) = v1;
        }
}

// ---------------- Flash attention with T5 bias + mask (fp32 SIMT) ----------------
#define AST 68
#define ATT_SMEM ((4 * 64 * AST + 32) * 4)

__global__ void __launch_bounds__(256) attn_kernel(
    const float* __restrict__ q, const float* __restrict__ k,
    const float* __restrict__ v, const int* __restrict__ xmask,
    const float* __restrict__ relb, const int* __restrict__ btab,
    float* __restrict__ o)
{
    extern __shared__ float sm[];
    float* Qs = sm;
    float* Ks = Qs + 64 * AST;
    float* Vs = Ks + 64 * AST;
    float* Ss = Vs + 64 * AST;
    float* sBias = Ss + 64 * AST;

    int qt = blockIdx.x, h = blockIdx.y, b = blockIdx.z;
    int tid = threadIdx.x;
    int tx = tid & 15, ty = tid >> 4;
    int r0 = ty << 2, c0 = tx << 2;
    int i0 = qt << 6;

    if (tid < 32) sBias[tid] = relb[tid * HH + h];

    const size_t base = (size_t)b * TT * DD + h * DH;

    for (int t = tid; t < 64 * 16; t += 256) {
        int rr = t >> 4, cc = (t & 15) << 2;
        float4 qv = *(const float4*)(q + base + (size_t)(i0 + rr) * DD + cc);
        Qs[rr * AST + cc + 0] = qv.x * 0.125f;
        Qs[rr * AST + cc + 1] = qv.y * 0.125f;
        Qs[rr * AST + cc + 2] = qv.z * 0.125f;
        Qs[rr * AST + cc + 3] = qv.w * 0.125f;
    }

    float acc[4][4];
#pragma unroll
    for (int i = 0; i < 4; i++)
#pragma unroll
        for (int j = 0; j < 4; j++) acc[i][j] = 0.f;
    float mprev[4] = {-1e30f, -1e30f, -1e30f, -1e30f};
    float lprev[4] = {0.f, 0.f, 0.f, 0.f};
    __syncthreads();

    for (int kt = 0; kt < TT / 64; kt++) {
        int j0 = kt << 6;
        for (int t = tid; t < 64 * 16; t += 256) {
            int rr = t >> 4, cc = (t & 15) << 2;
            *(float4*)&Ks[rr * AST + cc] = *(const float4*)(k + base + (size_t)(j0 + rr) * DD + cc);
            *(float4*)&Vs[rr * AST + cc] = *(const float4*)(v + base + (size_t)(j0 + rr) * DD + cc);
        }
        __syncthreads();

        float s[4][4];
#pragma unroll
        for (int i = 0; i < 4; i++)
#pragma unroll
            for (int j = 0; j < 4; j++) s[i][j] = 0.f;
#pragma unroll
        for (int d = 0; d < 64; d += 4) {
            float4 qa[4], kb[4];
#pragma unroll
            for (int i = 0; i < 4; i++) qa[i] = *(float4*)&Qs[(r0 + i) * AST + d];
#pragma unroll
            for (int j = 0; j < 4; j++) kb[j] = *(float4*)&Ks[(c0 + j) * AST + d];
#pragma unroll
            for (int i = 0; i < 4; i++)
#pragma unroll
                for (int j = 0; j < 4; j++)
                    s[i][j] += qa[i].x * kb[j].x + qa[i].y * kb[j].y
                             + qa[i].z * kb[j].z + qa[i].w * kb[j].w;
        }
#pragma unroll
        for (int i = 0; i < 4; i++) {
            int gi = i0 + r0 + i;
            const int* mrow = xmask + ((size_t)b * TT + gi) * TT + j0 + c0;
#pragma unroll
            for (int j = 0; j < 4; j++) {
                int gj = j0 + c0 + j;
                float bias = sBias[btab[gj - gi + 2047]];
                s[i][j] = (mrow[j] != 0) ? (s[i][j] + bias) : -1e9f;
            }
        }
#pragma unroll
        for (int i = 0; i < 4; i++) {
            float m = fmaxf(fmaxf(s[i][0], s[i][1]), fmaxf(s[i][2], s[i][3]));
            m = fmaxf(m, __shfl_xor_sync(0xffffffffu, m, 8, 16));
            m = fmaxf(m, __shfl_xor_sync(0xffffffffu, m, 4, 16));
            m = fmaxf(m, __shfl_xor_sync(0xffffffffu, m, 2, 16));
            m = fmaxf(m, __shfl_xor_sync(0xffffffffu, m, 1, 16));
            float mnew = fmaxf(mprev[i], m);
            float corr = __expf(mprev[i] - mnew);
            float ps = 0.f;
#pragma unroll
            for (int j = 0; j < 4; j++) { s[i][j] = __expf(s[i][j] - mnew); ps += s[i][j]; }
            ps += __shfl_xor_sync(0xffffffffu, ps, 8, 16);
            ps += __shfl_xor_sync(0xffffffffu, ps, 4, 16);
            ps += __shfl_xor_sync(0xffffffffu, ps, 2, 16);
            ps += __shfl_xor_sync(0xffffffffu, ps, 1, 16);
            lprev[i] = lprev[i] * corr + ps;
            mprev[i] = mnew;
#pragma unroll
            for (int j = 0; j < 4; j++) acc[i][j] *= corr;
#pragma unroll
            for (int j = 0; j < 4; j++) Ss[(r0 + i) * AST + c0 + j] = s[i][j];
        }
        __syncthreads();
#pragma unroll 8
        for (int c = 0; c < 64; c++) {
            float4 vv = *(float4*)&Vs[c * AST + c0];
#pragma unroll
            for (int i = 0; i < 4; i++) {
                float p = Ss[(r0 + i) * AST + c];
                acc[i][0] += p * vv.x;
                acc[i][1] += p * vv.y;
                acc[i][2] += p * vv.z;
                acc[i][3] += p * vv.w;
            }
        }
        __syncthreads();
    }
#pragma unroll
    for (int i = 0; i < 4; i++) {
        float invl = 1.f / lprev[i];
        float4 ov = make_float4(acc[i][0] * invl, acc[i][1] * invl,
                                acc[i][2] * invl, acc[i][3] * invl);
        *(float4*)(o + base + (size_t)(i0 + r0 + i) * DD + c0) = ov;
    }
}

// ---------------- launch ----------------
extern "C" void kernel_launch(void* const* d_in, const int* in_sizes, int n_in,
                              void* d_out, int out_size) {
    const float* x     = (const float*)d_in[0];
    const int*   xmask = (const int*)d_in[1];
    const float* n1w   = (const float*)d_in[3];
    const float* n3w   = (const float*)d_in[4];
    const float* wqW   = (const float*)d_in[5];
    const float* wqA   = (const float*)d_in[6];
    const float* wqB   = (const float*)d_in[7];
    const float* wkW   = (const float*)d_in[8];
    const float* wvW   = (const float*)d_in[9];
    const float* wvA   = (const float*)d_in[10];
    const float* wvB   = (const float*)d_in[11];
    const float* fcW   = (const float*)d_in[12];
    const float* fcA   = (const float*)d_in[13];
    const float* fcB   = (const float*)d_in[14];
    const float* relb  = (const float*)d_in[15];
    const float* w1W   = (const float*)d_in[16];
    const float* w1A   = (const float*)d_in[17];
    const float* w1B   = (const float*)d_in[18];
    const float* w2W   = (const float*)d_in[19];
    const float* w2A   = (const float*)d_in[20];
    const float* w2B   = (const float*)d_in[21];

    float* scratch = nullptr;
    int*   btab    = nullptr;
    cudaGetSymbolAddress((void**)&scratch, g_scratch);
    cudaGetSymbolAddress((void**)&btab, g_btab);

    float* q   = scratch + OFF_Q;
    float* k   = scratch + OFF_K;
    float* v   = scratch + OFF_V;
    float* o   = scratch + OFF_O;
    float* x1  = scratch + OFF_X1;
    float* h4  = scratch + OFF_H4;
    __nv_bfloat16* yhl  = (__nv_bfloat16*)(scratch + OFF_YHL);
    __nv_bfloat16* ohl  = (__nv_bfloat16*)(scratch + OFF_OHL);
    __nv_bfloat16* y3hl = (__nv_bfloat16*)(scratch + OFF_Y3HL);
    __nv_bfloat16* yghl = (__nv_bfloat16*)(scratch + OFF_YGHL);
    __nv_bfloat16* wqhl = (__nv_bfloat16*)(scratch + OFF_WQHL);
    __nv_bfloat16* wkhl = (__nv_bfloat16*)(scratch + OFF_WKHL);
    __nv_bfloat16* wvhl = (__nv_bfloat16*)(scratch + OFF_WVHL);
    __nv_bfloat16* wfchl= (__nv_bfloat16*)(scratch + OFF_WFCHL);
    __nv_bfloat16* w1hl = (__nv_bfloat16*)(scratch + OFF_W1HL);
    __nv_bfloat16* w2hl = (__nv_bfloat16*)(scratch + OFF_W2HL);

    float* out_x    = (float*)d_out;
    float* out_bias = out_x + (size_t)MM * DD;

    cudaFuncSetAttribute(attn_kernel, cudaFuncAttributeMaxDynamicSharedMemorySize, ATT_SMEM);
    cudaFuncSetAttribute(gemm_mma_kernel, cudaFuncAttributeMaxDynamicSharedMemorySize, GEMM_SMEM);

    // 1) bucket table + pos_bias output
    bucket_kernel<<<(4095 + 255) / 256, 256>>>(btab);
    posbias_kernel<<<(HH * TT * TT) / 256, 256>>>(relb, btab, out_bias);

    // 2) weights -> merged bf16 hi/lo
    merge_hl_kernel<<<(DD * DD) / 256, 256>>>(wqW, wqA, wqB, wqhl, DD, DD);
    merge_hl_kernel<<<(DD * DD) / 256, 256>>>(wvW, wvA, wvB, wvhl, DD, DD);
    merge_hl_kernel<<<(DD * DD) / 256, 256>>>(fcW, fcA, fcB, wfchl, DD, DD);
    merge_hl_kernel<<<(4 * DD * DD) / 256, 256>>>(w1W, w1A, w1B, w1hl, 4 * DD, DD);
    merge_hl_kernel<<<(2 * DD * DD) / 256, 256>>>(w2W, w2A, w2B, w2hl, DD, 2 * DD);
    convert_hl_kernel<<<(DD * DD) / 256, 256>>>(wkW, wkhl, DD, DD);

    // 3) attention block
    rmsnorm_hl_kernel<<<MM, 256>>>(x, n1w, yhl);
    {
        dim3 g(DD / 128, MM / 128);   // (8, 32)
        gemm_mma_kernel<<<g, 256, GEMM_SMEM>>>(yhl, wqhl, nullptr, q, MM, DD, DD);
        gemm_mma_kernel<<<g, 256, GEMM_SMEM>>>(yhl, wkhl, nullptr, k, MM, DD, DD);
        gemm_mma_kernel<<<g, 256, GEMM_SMEM>>>(yhl, wvhl, nullptr, v, MM, DD, DD);
    }
    {
        dim3 g(TT / 64, HH, BB);
        attn_kernel<<<g, 256, ATT_SMEM>>>(q, k, v, xmask, relb, btab, o);
    }
    convert_hl_kernel<<<(MM * DD) / 256, 256>>>(o, ohl, MM, DD);
    {
        dim3 g(DD / 128, MM / 128);
        gemm_mma_kernel<<<g, 256, GEMM_SMEM>>>(ohl, wfchl, x, x1, MM, DD, DD);
    }

    // 4) GEGLU MLP
    rmsnorm_hl_kernel<<<MM, 256>>>(x1, n3w, y3hl);
    {
        dim3 g(4 * DD / 128, MM / 128);   // (32, 32)
        gemm_mma_kernel<<<g, 256, GEMM_SMEM>>>(y3hl, w1hl, nullptr, h4, MM, 4 * DD, DD);
    }
    geglu_hl_kernel<<<(MM * 2048) / 256, 256>>>(h4, yghl);
    {
        dim3 g(DD / 128, MM / 128);
        gemm_mma_kernel<<<g, 256, GEMM_SMEM>>>(yghl, w2hl, x1, out_x, MM, DD, 2 * DD);
    }
}

// round 11
// speedup vs baseline: 3.9601x; 2.6985x over previous
#include <cuda_runtime.h>
#include <cuda_fp16.h>
#include <math.h>
#include <stdint.h>

// Problem constants
#define BB 2
#define TT 2048
#define DD 1024
#define HH 16
#define DH 64
#define MM (BB*TT)   // 4096 rows

// ---------------- scratch layout (float units) ----------------
#define OFF_QF   0u          // f16 [MM][DD]   (2M floats)
#define OFF_KF   2097152u
#define OFF_VF   4194304u
#define OFF_OF   6291456u
#define OFF_YF   8388608u
#define OFF_Y3F  10485760u
#define OFF_YGF  12582912u   // f16 [MM][2048] (4M floats)
#define OFF_X1   16777216u   // f32 [MM][DD]
#define OFF_H4   20971520u   // f32 [MM][4096] (16M floats)
#define OFF_WQ   37748736u   // f16 hi/lo [2048][1024] (1M floats)
#define OFF_WK   38797312u
#define OFF_WV   39845888u
#define OFF_WFC  40894464u
#define OFF_W1   41943040u   // f16 hi/lo [8192][1024] (4M floats)
#define OFF_W2   46137344u   // f16 hi/lo [2048][2048] (2M floats)
#define SCRATCH_TOTAL 48234496u

__device__ float    g_scratch[SCRATCH_TOTAL];
__device__ int      g_btab[4095];
__device__ uint32_t g_mbits[BB * TT * 64];   // 1 MB packed mask bits

// ================= portable PTX helpers =================
__device__ __forceinline__ uint32_t smem_u32(const void* p) {
    uint32_t a;
    asm("{ .reg .u64 t; cvta.to.shared.u64 t, %1; cvt.u32.u64 %0, t; }"
        : "=r"(a) : "l"(p));
    return a;
}

#define CP_ASYNC16(s, g) \
    asm volatile("cp.async.cg.shared.global [%0], [%1], 16;" :: "r"(s), "l"(g))
#define CP_COMMIT() asm volatile("cp.async.commit_group;")
#define CP_WAIT(n)  asm volatile("cp.async.wait_group %0;" :: "n"(n))

__device__ __forceinline__ void ldsm_x4(uint32_t* d, uint32_t a) {
    asm volatile("ldmatrix.sync.aligned.m8n8.x4.shared.b16 {%0,%1,%2,%3}, [%4];"
        : "=r"(d[0]), "=r"(d[1]), "=r"(d[2]), "=r"(d[3]) : "r"(a));
}
__device__ __forceinline__ void ldsm_x4_t(uint32_t* d, uint32_t a) {
    asm volatile("ldmatrix.sync.aligned.m8n8.x4.trans.shared.b16 {%0,%1,%2,%3}, [%4];"
        : "=r"(d[0]), "=r"(d[1]), "=r"(d[2]), "=r"(d[3]) : "r"(a));
}

__device__ __forceinline__ void mma_f16h(float* c, const uint32_t* a,
                                         uint32_t b0, uint32_t b1) {
    asm volatile(
        "mma.sync.aligned.m16n8k16.row.col.f32.f16.f16.f32 "
        "{%0,%1,%2,%3}, {%4,%5,%6,%7}, {%8,%9}, {%0,%1,%2,%3};"
        : "+f"(c[0]), "+f"(c[1]), "+f"(c[2]), "+f"(c[3])
        : "r"(a[0]), "r"(a[1]), "r"(a[2]), "r"(a[3]), "r"(b0), "r"(b1));
}

// ---------------- T5 relative bucket table ----------------
__global__ void bucket_kernel(int* btab) {
    int idx = blockIdx.x * 256 + threadIdx.x;
    if (idx >= 4095) return;
    int rel = idx - 2047;
    int b = (rel > 0) ? 16 : 0;
    int a = rel < 0 ? -rel : rel;
    if (a < 8) {
        b += a;
    } else {
        int large;
        if ((a & (a - 1)) == 0) {
            int e = 31 - __clz(a);
            large = 8 + 2 * (e - 3);
        } else {
            large = 8 + (int)(2.0 * (log2((double)a) - 3.0));
        }
        b += (large < 15) ? large : 15;
    }
    btab[idx] = b;
}

// ---------------- pos_bias output: [H, T, T], float4 vectorized ----------------
__global__ void posbias4_kernel(const float* __restrict__ relb,
                                const int* __restrict__ btab,
                                float4* __restrict__ out) {
    int idx = blockIdx.x * 256 + threadIdx.x;    // < H*T*T/4 = 16777216
    if (idx >= HH * TT * TT / 4) return;
    int h = idx >> 20;
    int r = idx & 1048575;        // (T*T/4)
    int i = r >> 9;
    int j4 = (r & 511) << 2;
    int base = j4 - i + 2047;
    float4 v;
    v.x = relb[btab[base + 0] * HH + h];
    v.y = relb[btab[base + 1] * HH + h];
    v.z = relb[btab[base + 2] * HH + h];
    v.w = relb[btab[base + 3] * HH + h];
    out[idx] = v;
}

// ---------------- pack mask to bits ----------------
__global__ void maskbits_kernel(const int* __restrict__ xmask,
                                uint32_t* __restrict__ mbits) {
    int idx = blockIdx.x * 256 + threadIdx.x;   // < B*T*64
    if (idx >= BB * TT * 64) return;
    int w = idx & 63;
    int bi = idx >> 6;                           // b*T + i
    const int* src = xmask + (size_t)bi * TT + w * 32;
    uint32_t bits = 0;
#pragma unroll
    for (int j = 0; j < 32; j++) bits |= (src[j] != 0 ? 1u : 0u) << j;
    mbits[idx] = bits;
}

// ---------------- LoRA merge -> f16 hi/lo (with scale) ----------------
__global__ void merge_hlf16_kernel(const float* __restrict__ W,
                                   const float* __restrict__ A,
                                   const float* __restrict__ Bm,
                                   __half* __restrict__ out, int N, int K,
                                   float scale) {
    int idx = blockIdx.x * 256 + threadIdx.x;
    if (idx >= N * K) return;
    int n = idx / K, kk = idx - n * K;
    float s = 0.f;
#pragma unroll
    for (int r = 0; r < 8; r++) s += Bm[n * 8 + r] * A[r * K + kk];
    float m = (W[idx] + 0.125f * s) * scale;
    __half hi = __float2half(m);
    out[(size_t)n * K + kk] = hi;
    out[(size_t)(N + n) * K + kk] = __float2half(m - __half2float(hi));
}

// ---------------- f32 weight -> f16 hi/lo (no lora) ----------------
__global__ void convert_hlf16_kernel(const float* __restrict__ in,
                                     __half* __restrict__ out, int rows, int cols) {
    int idx = blockIdx.x * 256 + threadIdx.x;
    if (idx >= rows * cols) return;
    int r = idx / cols, c = idx - r * cols;
    float v = in[idx];
    __half hi = __float2half(v);
    out[(size_t)r * cols + c] = hi;
    out[(size_t)(rows + r) * cols + c] = __float2half(v - __half2float(hi));
}

// ---------------- RMSNorm -> f16 (single) ----------------
__global__ void rmsnorm_f16_kernel(const float* __restrict__ x,
                                   const float* __restrict__ w,
                                   __half* __restrict__ y) {
    int row = blockIdx.x;
    const float* xp = x + (size_t)row * DD;
    float ss = 0.f;
    for (int d = threadIdx.x; d < DD; d += 256) { float v = xp[d]; ss += v * v; }
    __shared__ float red[256];
    red[threadIdx.x] = ss;
    __syncthreads();
    for (int s = 128; s > 0; s >>= 1) {
        if (threadIdx.x < s) red[threadIdx.x] += red[threadIdx.x + s];
        __syncthreads();
    }
    float inv = rsqrtf(red[0] * (1.0f / DD) + 1e-6f);
    for (int d = threadIdx.x; d < DD; d += 256)
        y[(size_t)row * DD + d] = __float2half(w[d] * xp[d] * inv);
}

// ---------------- GEGLU -> f16 (single) ----------------
__global__ void geglu_f16_kernel(const float* __restrict__ h,
                                 __half* __restrict__ yg) {
    int idx = blockIdx.x * 256 + threadIdx.x;
    if (idx >= MM * 2048) return;
    int m = idx >> 11, c = idx & 2047;
    float p1 = h[(size_t)m * 4096 + c];
    float p2 = h[(size_t)m * 4096 + 2048 + c];
    float u = 0.7978845608f * (p2 + 0.044715f * p2 * p2 * p2);
    float g = 0.5f * p2 * (1.f + tanhf(u));
    yg[idx] = __float2half(p1 * g);
}

// ================= mma.sync f16 GEMM (A single, W hi/lo: 2 passes) =================
// C[M,N] = A[M,K] @ (Wh+Wl)[N,K]^T  (+res f32, or f16 output)
// Tile 128x128, BK=32, 256 threads = 8 warps (4M x 2N), warp tile 32x64.
#define GP      40                // padded smem stride in halves
#define GBUF    (128 * GP * 2)    // 10240 B per operand buffer
#define GSTAGE  (3 * GBUF)        // A, Wh, Wl
#define GEMM_SMEM (2 * GSTAGE)    // 61440 B

__device__ __forceinline__ void load_chunk_g(
    const __half* Af, const __half* Whl, int K, int Ntot,
    int bm, int bn, int k0, uint32_t sstage, int tid)
{
#pragma unroll
    for (int i = 0; i < 6; i++) {
        int idx = tid + 256 * i;        // 0..1535
        int buf = idx >> 9;             // 0:A 1:Wh 2:Wl
        int rem = idx & 511;
        int r = rem >> 2, cg = rem & 3;
        const __half* src;
        if (buf == 0)      src = Af  + (size_t)(bm + r) * K + k0 + cg * 8;
        else if (buf == 1) src = Whl + (size_t)(bn + r) * K + k0 + cg * 8;
        else               src = Whl + (size_t)(Ntot + bn + r) * K + k0 + cg * 8;
        CP_ASYNC16(sstage + (uint32_t)(buf * GBUF + r * (GP * 2) + cg * 16),
                   (const char*)src);
    }
}

__global__ void __launch_bounds__(256, 1) gemm_f16_kernel(
    const __half* __restrict__ Af, const __half* __restrict__ Whl,
    const float* __restrict__ res, float* __restrict__ Cf,
    __half* __restrict__ Ch,
    int Mtot, int Ntot, int K)
{
    extern __shared__ char gsm[];
    uint32_t sb = smem_u32(gsm);
    int tid = threadIdx.x;
    int lane = tid & 31, w = tid >> 5;
    int wm = (w & 3) * 32, wn = (w >> 2) * 64;
    int bm = blockIdx.y * 128, bn = blockIdx.x * 128;

    float acc[2][8][4];
#pragma unroll
    for (int mt = 0; mt < 2; mt++)
#pragma unroll
        for (int nt = 0; nt < 8; nt++)
#pragma unroll
            for (int e = 0; e < 4; e++) acc[mt][nt][e] = 0.f;

    int nc = K / 32;
    load_chunk_g(Af, Whl, K, Ntot, bm, bn, 0, sb, tid);
    CP_COMMIT();

    for (int c = 0; c < nc; c++) {
        int s = c & 1;
        if (c + 1 < nc) {
            load_chunk_g(Af, Whl, K, Ntot, bm, bn, (c + 1) * 32,
                         sb + (uint32_t)((s ^ 1) * GSTAGE), tid);
            CP_COMMIT();
            CP_WAIT(1);
        } else {
            CP_WAIT(0);
        }
        __syncthreads();
        uint32_t st = sb + (uint32_t)(s * GSTAGE);
#pragma unroll
        for (int ks = 0; ks < 2; ks++) {
            int k0 = ks * 16;
            uint32_t a[2][4], bh[4][4], bl[4][4];
#pragma unroll
            for (int mt = 0; mt < 2; mt++) {
                uint32_t row = (uint32_t)(wm + mt * 16 + (lane & 15));
                uint32_t col = (uint32_t)(k0 + ((lane >> 4) << 3));
                ldsm_x4(a[mt], st + row * (GP * 2) + col * 2);
            }
#pragma unroll
            for (int g = 0; g < 4; g++) {
                uint32_t grp = (uint32_t)(lane >> 3);
                uint32_t row = (uint32_t)(wn + g * 16) + ((grp >> 1) << 3) + (uint32_t)(lane & 7);
                uint32_t col = (uint32_t)k0 + ((grp & 1) << 3);
                uint32_t off = row * (GP * 2) + col * 2;
                ldsm_x4(bh[g], st + GBUF + off);
                ldsm_x4(bl[g], st + 2 * GBUF + off);
            }
#pragma unroll
            for (int mt = 0; mt < 2; mt++)
#pragma unroll
                for (int nt = 0; nt < 8; nt++) {
                    uint32_t b0h = bh[nt >> 1][(nt & 1) * 2];
                    uint32_t b1h = bh[nt >> 1][(nt & 1) * 2 + 1];
                    uint32_t b0l = bl[nt >> 1][(nt & 1) * 2];
                    uint32_t b1l = bl[nt >> 1][(nt & 1) * 2 + 1];
                    mma_f16h(acc[mt][nt], a[mt], b0h, b1h);
                    mma_f16h(acc[mt][nt], a[mt], b0l, b1l);
                }
        }
        __syncthreads();
    }

    // epilogue
#pragma unroll
    for (int mt = 0; mt < 2; mt++)
#pragma unroll
        for (int nt = 0; nt < 8; nt++) {
            int m0 = bm + wm + mt * 16 + (lane >> 2);
            int n  = bn + wn + nt * 8 + ((lane & 3) << 1);
            size_t i0 = (size_t)m0 * Ntot + n;
            size_t i1 = (size_t)(m0 + 8) * Ntot + n;
            if (Ch) {
                *(__half2*)(Ch + i0) = __floats2half2_rn(acc[mt][nt][0], acc[mt][nt][1]);
                *(__half2*)(Ch + i1) = __floats2half2_rn(acc[mt][nt][2], acc[mt][nt][3]);
            } else {
                float2 v0 = make_float2(acc[mt][nt][0], acc[mt][nt][1]);
                float2 v1 = make_float2(acc[mt][nt][2], acc[mt][nt][3]);
                if (res) {
                    float2 r0 = *(const float2*)(res + i0);
                    float2 r1 = *(const float2*)(res + i1);
                    v0.x += r0.x; v0.y += r0.y;
                    v1.x += r1.x; v1.y += r1.y;
                }
                *(float2*)(Cf + i0) = v0;
                *(float2*)(Cf + i1) = v1;
            }
        }
}

// ================= tensor-core flash attention (f16) =================
// Grid (T/128, H, B), 256 threads = 8 warps; warp owns 16 query rows.
// Q pre-scaled by 1/8 (folded into Wq).
#define QP 72     // Q/K/V smem stride (halves)
#define PP 136    // P smem stride (halves)
// smem half offsets
#define SQ_OFF 0
#define SK_OFF 9216
#define SV_OFF 18432
#define SP_OFF 27648
#define SP_END (27648 + 128 * PP)          // 45056 halves
#define BIAS_BYTE (SP_END * 2)             // 90112
#define SBIAS_BYTE (BIAS_BYTE + 4096 * 4)  // 106496
#define MW_BYTE (SBIAS_BYTE + 32 * 4)      // 106624
#define ATT_SMEM (MW_BYTE + 512 * 4)       // 108672

__global__ void __launch_bounds__(256, 1) attn_tc_kernel(
    const __half* __restrict__ qf, const __half* __restrict__ kf,
    const __half* __restrict__ vf, const uint32_t* __restrict__ mbits,
    const float* __restrict__ relb, const int* __restrict__ btab,
    __half* __restrict__ of)
{
    extern __shared__ char asmem[];
    uint32_t sb = smem_u32(asmem);
    float* biasAll = (float*)(asmem + BIAS_BYTE);
    float* sBias   = (float*)(asmem + SBIAS_BYTE);
    uint32_t* mwp  = (uint32_t*)(asmem + MW_BYTE);

    int qt = blockIdx.x, h = blockIdx.y, b = blockIdx.z;
    int tid = threadIdx.x;
    int lane = tid & 31, w = tid >> 5;
    int i0 = qt * 128;

    if (tid < 32) sBias[tid] = relb[tid * HH + h];
    __syncthreads();
    for (int u = tid; u < 4095; u += 256) biasAll[u] = sBias[btab[u]];

    // load Q tile (128 x 64 halves)
    size_t qbase = ((size_t)b * TT + i0) * DD + h * 64;
#pragma unroll
    for (int i = 0; i < 4; i++) {
        int c = tid + 256 * i;          // 0..1023
        int r = c >> 3, cg = c & 7;
        CP_ASYNC16(sb + (uint32_t)((SQ_OFF + r * QP + cg * 8) * 2),
                   (const char*)(qf + qbase + (size_t)r * DD + cg * 8));
    }
    CP_COMMIT(); CP_WAIT(0);
    __syncthreads();

    // preload Q fragments (warp rows w*16..w*16+15, k 0..63)
    uint32_t aq[4][4];
#pragma unroll
    for (int ks = 0; ks < 4; ks++) {
        uint32_t row = (uint32_t)(w * 16 + (lane & 15));
        uint32_t col = (uint32_t)(ks * 16 + ((lane >> 4) << 3));
        ldsm_x4(aq[ks], sb + (SQ_OFF + row * QP + col) * 2);
    }

    float o[8][4];
#pragma unroll
    for (int nt = 0; nt < 8; nt++)
#pragma unroll
        for (int e = 0; e < 4; e++) o[nt][e] = 0.f;
    float m0p = -1e30f, m1p = -1e30f, l0 = 0.f, l1 = 0.f;
    int rl0 = w * 16 + (lane >> 2);

    for (int kt = 0; kt < TT / 128; kt++) {
        int j0 = kt * 128;
        // K/V tiles via cp.async
        size_t kvbase = ((size_t)b * TT + j0) * DD + h * 64;
#pragma unroll
        for (int i = 0; i < 8; i++) {
            int c = tid + 256 * i;      // 0..2047
            int buf = c >> 10, r = (c >> 3) & 127, cg = c & 7;
            const __half* srcp = (buf ? vf : kf) + kvbase + (size_t)r * DD + cg * 8;
            uint32_t dst = sb + (uint32_t)(((buf ? SV_OFF : SK_OFF) + r * QP + cg * 8) * 2);
            CP_ASYNC16(dst, (const char*)srcp);
        }
        CP_COMMIT();
        // mask words (plain LDG -> STS)
#pragma unroll
        for (int i = 0; i < 2; i++) {
            int idx = tid + 256 * i;    // 0..511
            int r = idx >> 2, ws = idx & 3;
            mwp[idx] = mbits[(size_t)(b * TT + i0 + r) * 64 + (j0 >> 5) + ws];
        }
        CP_WAIT(0);
        __syncthreads();

        // ---- S = Q K^T ----
        float s[16][4];
#pragma unroll
        for (int t = 0; t < 16; t++)
#pragma unroll
            for (int e = 0; e < 4; e++) s[t][e] = 0.f;
#pragma unroll
        for (int ks = 0; ks < 4; ks++) {
#pragma unroll
            for (int g = 0; g < 8; g++) {
                uint32_t grp = (uint32_t)(lane >> 3);
                uint32_t row = (uint32_t)(g * 16) + ((grp >> 1) << 3) + (uint32_t)(lane & 7);
                uint32_t col = (uint32_t)(ks * 16) + ((grp & 1) << 3);
                uint32_t bk[4];
                ldsm_x4(bk, sb + (SK_OFF + row * QP + col) * 2);
                mma_f16h(s[g * 2 + 0], aq[ks], bk[0], bk[1]);
                mma_f16h(s[g * 2 + 1], aq[ks], bk[2], bk[3]);
            }
        }

        // ---- bias + mask ----
        int ub = 2047 + j0 - i0;
        uint32_t mA[4], mB[4];
#pragma unroll
        for (int k2 = 0; k2 < 4; k2++) {
            mA[k2] = mwp[rl0 * 4 + k2];
            mB[k2] = mwp[(rl0 + 8) * 4 + k2];
        }
#pragma unroll
        for (int t = 0; t < 16; t++) {
            int cjb = t * 8 + ((lane & 3) << 1);
#pragma unroll
            for (int e = 0; e < 4; e++) {
                int cj = cjb + (e & 1);
                int rl = (e < 2) ? rl0 : rl0 + 8;
                float val = s[t][e] + biasAll[ub + cj - rl];
                uint32_t mv = ((e < 2) ? mA : mB)[cj >> 5];
                s[t][e] = ((mv >> (cj & 31)) & 1u) ? val : -1e9f;
            }
        }

        // ---- online softmax (warp-local rows) ----
        float mx0 = -1e30f, mx1 = -1e30f;
#pragma unroll
        for (int t = 0; t < 16; t++) {
            mx0 = fmaxf(mx0, fmaxf(s[t][0], s[t][1]));
            mx1 = fmaxf(mx1, fmaxf(s[t][2], s[t][3]));
        }
        mx0 = fmaxf(mx0, __shfl_xor_sync(0xffffffffu, mx0, 1));
        mx0 = fmaxf(mx0, __shfl_xor_sync(0xffffffffu, mx0, 2));
        mx1 = fmaxf(mx1, __shfl_xor_sync(0xffffffffu, mx1, 1));
        mx1 = fmaxf(mx1, __shfl_xor_sync(0xffffffffu, mx1, 2));
        float mn0 = fmaxf(m0p, mx0), mn1 = fmaxf(m1p, mx1);
        float corr0 = __expf(m0p - mn0), corr1 = __expf(m1p - mn1);
        float sm0 = 0.f, sm1 = 0.f;
#pragma unroll
        for (int t = 0; t < 16; t++) {
            float p0 = __expf(s[t][0] - mn0);
            float p1 = __expf(s[t][1] - mn0);
            float p2 = __expf(s[t][2] - mn1);
            float p3 = __expf(s[t][3] - mn1);
            sm0 += p0 + p1; sm1 += p2 + p3;
            int cb = t * 8 + ((lane & 3) << 1);
            *(__half2*)(asmem + (SP_OFF + rl0 * PP + cb) * 2)       = __floats2half2_rn(p0, p1);
            *(__half2*)(asmem + (SP_OFF + (rl0 + 8) * PP + cb) * 2) = __floats2half2_rn(p2, p3);
        }
        sm0 += __shfl_xor_sync(0xffffffffu, sm0, 1);
        sm0 += __shfl_xor_sync(0xffffffffu, sm0, 2);
        sm1 += __shfl_xor_sync(0xffffffffu, sm1, 1);
        sm1 += __shfl_xor_sync(0xffffffffu, sm1, 2);
        l0 = l0 * corr0 + sm0;
        l1 = l1 * corr1 + sm1;
        m0p = mn0; m1p = mn1;
#pragma unroll
        for (int nt = 0; nt < 8; nt++) {
            o[nt][0] *= corr0; o[nt][1] *= corr0;
            o[nt][2] *= corr1; o[nt][3] *= corr1;
        }
        __syncwarp();

        // ---- O += P V ----
#pragma unroll
        for (int ks = 0; ks < 8; ks++) {
            uint32_t ap[4];
            {
                uint32_t row = (uint32_t)(w * 16 + (lane & 15));
                uint32_t col = (uint32_t)(ks * 16 + ((lane >> 4) << 3));
                ldsm_x4(ap, sb + (SP_OFF + row * PP + col) * 2);
            }
#pragma unroll
            for (int g = 0; g < 4; g++) {
                uint32_t row = (uint32_t)(ks * 16 + (lane & 15));
                uint32_t col = (uint32_t)(g * 16 + ((lane >> 4) << 3));
                uint32_t bv[4];
                ldsm_x4_t(bv, sb + (SV_OFF + row * QP + col) * 2);
                mma_f16h(o[g * 2 + 0], ap, bv[0], bv[1]);
                mma_f16h(o[g * 2 + 1], ap, bv[2], bv[3]);
            }
        }
        __syncthreads();   // protect K/V/mask for next tile
    }

    // ---- epilogue ----
    float il0 = 1.f / l0, il1 = 1.f / l1;
    size_t r0g = ((size_t)b * TT + i0 + rl0) * DD + h * 64;
    size_t r1g = r0g + (size_t)8 * DD;
#pragma unroll
    for (int nt = 0; nt < 8; nt++) {
        int col = nt * 8 + ((lane & 3) << 1);
        *(__half2*)(of + r0g + col) = __floats2half2_rn(o[nt][0] * il0, o[nt][1] * il0);
        *(__half2*)(of + r1g + col) = __floats2half2_rn(o[nt][2] * il1, o[nt][3] * il1);
    }
}

// ---------------- launch ----------------
extern "C" void kernel_launch(void* const* d_in, const int* in_sizes, int n_in,
                              void* d_out, int out_size) {
    const float* x     = (const float*)d_in[0];
    const int*   xmask = (const int*)d_in[1];
    const float* n1w   = (const float*)d_in[3];
    const float* n3w   = (const float*)d_in[4];
    const float* wqW   = (const float*)d_in[5];
    const float* wqA   = (const float*)d_in[6];
    const float* wqB   = (const float*)d_in[7];
    const float* wkW   = (const float*)d_in[8];
    const float* wvW   = (const float*)d_in[9];
    const float* wvA   = (const float*)d_in[10];
    const float* wvB   = (const float*)d_in[11];
    const float* fcW   = (const float*)d_in[12];
    const float* fcA   = (const float*)d_in[13];
    const float* fcB   = (const float*)d_in[14];
    const float* relb  = (const float*)d_in[15];
    const float* w1W   = (const float*)d_in[16];
    const float* w1A   = (const float*)d_in[17];
    const float* w1B   = (const float*)d_in[18];
    const float* w2W   = (const float*)d_in[19];
    const float* w2A   = (const float*)d_in[20];
    const float* w2B   = (const float*)d_in[21];

    float* scratch = nullptr;
    int* btab = nullptr;
    uint32_t* mbits = nullptr;
    cudaGetSymbolAddress((void**)&scratch, g_scratch);
    cudaGetSymbolAddress((void**)&btab, g_btab);
    cudaGetSymbolAddress((void**)&mbits, g_mbits);

    __half* qfp  = (__half*)(scratch + OFF_QF);
    __half* kfp  = (__half*)(scratch + OFF_KF);
    __half* vfp  = (__half*)(scratch + OFF_VF);
    __half* ofp  = (__half*)(scratch + OFF_OF);
    __half* yf   = (__half*)(scratch + OFF_YF);
    __half* y3f  = (__half*)(scratch + OFF_Y3F);
    __half* ygf  = (__half*)(scratch + OFF_YGF);
    float*  x1   = scratch + OFF_X1;
    float*  h4   = scratch + OFF_H4;
    __half* wq   = (__half*)(scratch + OFF_WQ);
    __half* wk   = (__half*)(scratch + OFF_WK);
    __half* wv   = (__half*)(scratch + OFF_WV);
    __half* wfc  = (__half*)(scratch + OFF_WFC);
    __half* w1   = (__half*)(scratch + OFF_W1);
    __half* w2   = (__half*)(scratch + OFF_W2);

    float* out_x    = (float*)d_out;
    float* out_bias = out_x + (size_t)MM * DD;

    cudaFuncSetAttribute(gemm_f16_kernel, cudaFuncAttributeMaxDynamicSharedMemorySize, GEMM_SMEM);
    cudaFuncSetAttribute(attn_tc_kernel, cudaFuncAttributeMaxDynamicSharedMemorySize, ATT_SMEM);

    // 1) tables + big bias output + mask bits
    bucket_kernel<<<(4095 + 255) / 256, 256>>>(btab);
    posbias4_kernel<<<(HH * TT * TT / 4) / 256, 256>>>(relb, btab, (float4*)out_bias);
    maskbits_kernel<<<(BB * TT * 64) / 256, 256>>>(xmask, mbits);

    // 2) weights -> f16 hi/lo (q gets 0.125 scale folded in)
    merge_hlf16_kernel<<<(DD * DD) / 256, 256>>>(wqW, wqA, wqB, wq, DD, DD, 0.125f);
    merge_hlf16_kernel<<<(DD * DD) / 256, 256>>>(wvW, wvA, wvB, wv, DD, DD, 1.0f);
    merge_hlf16_kernel<<<(DD * DD) / 256, 256>>>(fcW, fcA, fcB, wfc, DD, DD, 1.0f);
    merge_hlf16_kernel<<<(4 * DD * DD) / 256, 256>>>(w1W, w1A, w1B, w1, 4 * DD, DD, 1.0f);
    merge_hlf16_kernel<<<(2 * DD * DD) / 256, 256>>>(w2W, w2A, w2B, w2, DD, 2 * DD, 1.0f);
    convert_hlf16_kernel<<<(DD * DD) / 256, 256>>>(wkW, wk, DD, DD);

    // 3) attention block
    rmsnorm_f16_kernel<<<MM, 256>>>(x, n1w, yf);
    {
        dim3 g(DD / 128, MM / 128);
        gemm_f16_kernel<<<g, 256, GEMM_SMEM>>>(yf, wq, nullptr, nullptr, qfp, MM, DD, DD);
        gemm_f16_kernel<<<g, 256, GEMM_SMEM>>>(yf, wk, nullptr, nullptr, kfp, MM, DD, DD);
        gemm_f16_kernel<<<g, 256, GEMM_SMEM>>>(yf, wv, nullptr, nullptr, vfp, MM, DD, DD);
    }
    {
        dim3 g(TT / 128, HH, BB);
        attn_tc_kernel<<<g, 256, ATT_SMEM>>>(qfp, kfp, vfp, mbits, relb, btab, ofp);
    }
    {
        dim3 g(DD / 128, MM / 128);
        gemm_f16_kernel<<<g, 256, GEMM_SMEM>>>(ofp, wfc, x, x1, nullptr, MM, DD, DD);
    }

    // 4) GEGLU MLP
    rmsnorm_f16_kernel<<<MM, 256>>>(x1, n3w, y3f);
    {
        dim3 g(4 * DD / 128, MM / 128);
        gemm_f16_kernel<<<g, 256, GEMM_SMEM>>>(y3f, w1, nullptr, h4, nullptr, MM, 4 * DD, DD);
    }
    geglu_f16_kernel<<<(MM * 2048) / 256, 256>>>(h4, ygf);
    {
        dim3 g(DD / 128, MM / 128);
        gemm_f16_kernel<<<g, 256, GEMM_SMEM>>>(ygf, w2, x1, out_x, nullptr, MM, DD, 2 * DD);
    }
}

// round 12
// speedup vs baseline: 4.8534x; 1.2256x over previous
#include <cuda_runtime.h>
#include <cuda_fp16.h>
#include <math.h>
#include <stdint.h>

// Problem constants
#define BB 2
#define TT 2048
#define DD 1024
#define HH 16
#define DH 64
#define MM (BB*TT)   // 4096 rows

// ---------------- scratch layout (float units) ----------------
#define OFF_QF   0u          // f16 [MM][DD]
#define OFF_KF   2097152u
#define OFF_VF   4194304u
#define OFF_OF   6291456u
#define OFF_YF   8388608u
#define OFF_Y3F  10485760u
#define OFF_YGF  12582912u   // f16 [MM][2048]
#define OFF_X1   16777216u   // f32 [MM][DD]
#define OFF_H4F  20971520u   // f16 [MM][4096]
#define OFF_WQ   29360128u   // f16 [1024][1024]
#define OFF_WK   29884416u
#define OFF_WV   30408704u
#define OFF_WFC  30932992u
#define OFF_W1   31457280u   // f16 [4096][1024]
#define OFF_W2   33554432u   // f16 [1024][2048]
#define SCRATCH_TOTAL 34603008u

__device__ float    g_scratch[SCRATCH_TOTAL];
__device__ int      g_btab[4095];
__device__ uint32_t g_mbits[BB * TT * 64];   // 1 MB packed mask bits

// ================= portable PTX helpers =================
__device__ __forceinline__ uint32_t smem_u32(const void* p) {
    uint32_t a;
    asm("{ .reg .u64 t; cvta.to.shared.u64 t, %1; cvt.u32.u64 %0, t; }"
        : "=r"(a) : "l"(p));
    return a;
}

#define CP_ASYNC16(s, g) \
    asm volatile("cp.async.cg.shared.global [%0], [%1], 16;" :: "r"(s), "l"(g))
#define CP_COMMIT() asm volatile("cp.async.commit_group;")
#define CP_WAIT(n)  asm volatile("cp.async.wait_group %0;" :: "n"(n))

__device__ __forceinline__ void ldsm_x4(uint32_t* d, uint32_t a) {
    asm volatile("ldmatrix.sync.aligned.m8n8.x4.shared.b16 {%0,%1,%2,%3}, [%4];"
        : "=r"(d[0]), "=r"(d[1]), "=r"(d[2]), "=r"(d[3]) : "r"(a));
}
__device__ __forceinline__ void ldsm_x4_t(uint32_t* d, uint32_t a) {
    asm volatile("ldmatrix.sync.aligned.m8n8.x4.trans.shared.b16 {%0,%1,%2,%3}, [%4];"
        : "=r"(d[0]), "=r"(d[1]), "=r"(d[2]), "=r"(d[3]) : "r"(a));
}

__device__ __forceinline__ void mma_f16h(float* c, const uint32_t* a,
                                         uint32_t b0, uint32_t b1) {
    asm volatile(
        "mma.sync.aligned.m16n8k16.row.col.f32.f16.f16.f32 "
        "{%0,%1,%2,%3}, {%4,%5,%6,%7}, {%8,%9}, {%0,%1,%2,%3};"
        : "+f"(c[0]), "+f"(c[1]), "+f"(c[2]), "+f"(c[3])
        : "r"(a[0]), "r"(a[1]), "r"(a[2]), "r"(a[3]), "r"(b0), "r"(b1));
}

// ---------------- T5 relative bucket table ----------------
__global__ void bucket_kernel(int* btab) {
    int idx = blockIdx.x * 256 + threadIdx.x;
    if (idx >= 4095) return;
    int rel = idx - 2047;
    int b = (rel > 0) ? 16 : 0;
    int a = rel < 0 ? -rel : rel;
    if (a < 8) {
        b += a;
    } else {
        int large;
        if ((a & (a - 1)) == 0) {
            int e = 31 - __clz(a);
            large = 8 + 2 * (e - 3);
        } else {
            large = 8 + (int)(2.0 * (log2((double)a) - 3.0));
        }
        b += (large < 15) ? large : 15;
    }
    btab[idx] = b;
}

// ---------------- pos_bias output: [H, T, T], float4 vectorized ----------------
__global__ void posbias4_kernel(const float* __restrict__ relb,
                                const int* __restrict__ btab,
                                float4* __restrict__ out) {
    int idx = blockIdx.x * 256 + threadIdx.x;    // < H*T*T/4
    if (idx >= HH * TT * TT / 4) return;
    int h = idx >> 20;
    int r = idx & 1048575;
    int i = r >> 9;
    int j4 = (r & 511) << 2;
    int base = j4 - i + 2047;
    float4 v;
    v.x = relb[btab[base + 0] * HH + h];
    v.y = relb[btab[base + 1] * HH + h];
    v.z = relb[btab[base + 2] * HH + h];
    v.w = relb[btab[base + 3] * HH + h];
    out[idx] = v;
}

// ---------------- pack mask to bits ----------------
__global__ void maskbits_kernel(const int* __restrict__ xmask,
                                uint32_t* __restrict__ mbits) {
    int idx = blockIdx.x * 256 + threadIdx.x;   // < B*T*64
    if (idx >= BB * TT * 64) return;
    int w = idx & 63;
    int bi = idx >> 6;
    const int* src = xmask + (size_t)bi * TT + w * 32;
    uint32_t bits = 0;
#pragma unroll
    for (int j = 0; j < 32; j++) bits |= (src[j] != 0 ? 1u : 0u) << j;
    mbits[idx] = bits;
}

// ---------------- LoRA merge -> f16 (single, with scale) ----------------
__global__ void merge_f16_kernel(const float* __restrict__ W,
                                 const float* __restrict__ A,
                                 const float* __restrict__ Bm,
                                 __half* __restrict__ out, int N, int K,
                                 float scale) {
    int idx = blockIdx.x * 256 + threadIdx.x;
    if (idx >= N * K) return;
    int n = idx / K, kk = idx - n * K;
    float s = 0.f;
#pragma unroll
    for (int r = 0; r < 8; r++) s += Bm[n * 8 + r] * A[r * K + kk];
    out[idx] = __float2half((W[idx] + 0.125f * s) * scale);
}

// ---------------- f32 -> f16 (no lora) ----------------
__global__ void convert_f16_kernel(const float* __restrict__ in,
                                   __half* __restrict__ out, int n) {
    int idx = blockIdx.x * 256 + threadIdx.x;
    if (idx < n) out[idx] = __float2half(in[idx]);
}

// ---------------- RMSNorm -> f16 ----------------
__global__ void rmsnorm_f16_kernel(const float* __restrict__ x,
                                   const float* __restrict__ w,
                                   __half* __restrict__ y) {
    int row = blockIdx.x;
    const float* xp = x + (size_t)row * DD;
    float ss = 0.f;
    for (int d = threadIdx.x; d < DD; d += 256) { float v = xp[d]; ss += v * v; }
    __shared__ float red[256];
    red[threadIdx.x] = ss;
    __syncthreads();
    for (int s = 128; s > 0; s >>= 1) {
        if (threadIdx.x < s) red[threadIdx.x] += red[threadIdx.x + s];
        __syncthreads();
    }
    float inv = rsqrtf(red[0] * (1.0f / DD) + 1e-6f);
    for (int d = threadIdx.x; d < DD; d += 256)
        y[(size_t)row * DD + d] = __float2half(w[d] * xp[d] * inv);
}

// ---------------- GEGLU (f16 in) -> f16 ----------------
__global__ void geglu_f16_kernel(const __half* __restrict__ h,
                                 __half* __restrict__ yg) {
    int idx = blockIdx.x * 256 + threadIdx.x;
    if (idx >= MM * 2048) return;
    int m = idx >> 11, c = idx & 2047;
    float p1 = __half2float(h[(size_t)m * 4096 + c]);
    float p2 = __half2float(h[(size_t)m * 4096 + 2048 + c]);
    float u = 0.7978845608f * (p2 + 0.044715f * p2 * p2 * p2);
    float g = 0.5f * p2 * (1.f + tanhf(u));
    yg[idx] = __float2half(p1 * g);
}

// ================= mma.sync f16 GEMM (single pass, 3-stage pipeline) =================
// C[M,N] = A[M,K] @ W[N,K]^T  (+res f32 -> f32 out, or f16 out)
// Tile 128x128, BK=32, 256 threads = 8 warps (4M x 2N), warp tile 32x64.
#define GP      40                // padded smem stride in halves
#define GBUF    (128 * GP * 2)    // 10240 B per operand buffer
#define GSTAGE  (2 * GBUF)        // A, W
#define GEMM_SMEM (3 * GSTAGE)    // 61440 B

__device__ __forceinline__ void load_chunk_g(
    const __half* Af, const __half* Wf, int K,
    int bm, int bn, int k0, uint32_t sstage, int tid)
{
#pragma unroll
    for (int i = 0; i < 4; i++) {
        int idx = tid + 256 * i;        // 0..1023
        int buf = idx >> 9;             // 0:A 1:W
        int rem = idx & 511;
        int r = rem >> 2, cg = rem & 3;
        const __half* src = buf ? (Wf + (size_t)(bn + r) * K + k0 + cg * 8)
                                : (Af + (size_t)(bm + r) * K + k0 + cg * 8);
        CP_ASYNC16(sstage + (uint32_t)(buf * GBUF + r * (GP * 2) + cg * 16),
                   (const char*)src);
    }
}

__global__ void __launch_bounds__(256, 1) gemm_f16_kernel(
    const __half* __restrict__ Af, const __half* __restrict__ Wf,
    const float* __restrict__ res, float* __restrict__ Cf,
    __half* __restrict__ Ch,
    int Mtot, int Ntot, int K)
{
    extern __shared__ char gsm[];
    uint32_t sb = smem_u32(gsm);
    int tid = threadIdx.x;
    int lane = tid & 31, w = tid >> 5;
    int wm = (w & 3) * 32, wn = (w >> 2) * 64;
    int bm = blockIdx.y * 128, bn = blockIdx.x * 128;

    float acc[2][8][4];
#pragma unroll
    for (int mt = 0; mt < 2; mt++)
#pragma unroll
        for (int nt = 0; nt < 8; nt++)
#pragma unroll
            for (int e = 0; e < 4; e++) acc[mt][nt][e] = 0.f;

    int nc = K / 32;
    load_chunk_g(Af, Wf, K, bm, bn, 0, sb, tid);
    CP_COMMIT();
    load_chunk_g(Af, Wf, K, bm, bn, 32, sb + GSTAGE, tid);
    CP_COMMIT();

    for (int c = 0; c < nc; c++) {
        if (c + 1 < nc) { CP_WAIT(1); } else { CP_WAIT(0); }
        __syncthreads();
        uint32_t st = sb + (uint32_t)((c % 3) * GSTAGE);
#pragma unroll
        for (int ks = 0; ks < 2; ks++) {
            int k0 = ks * 16;
            uint32_t a[2][4], bh[4][4];
#pragma unroll
            for (int mt = 0; mt < 2; mt++) {
                uint32_t row = (uint32_t)(wm + mt * 16 + (lane & 15));
                uint32_t col = (uint32_t)(k0 + ((lane >> 4) << 3));
                ldsm_x4(a[mt], st + row * (GP * 2) + col * 2);
            }
#pragma unroll
            for (int g = 0; g < 4; g++) {
                uint32_t grp = (uint32_t)(lane >> 3);
                uint32_t row = (uint32_t)(wn + g * 16) + ((grp >> 1) << 3) + (uint32_t)(lane & 7);
                uint32_t col = (uint32_t)k0 + ((grp & 1) << 3);
                ldsm_x4(bh[g], st + GBUF + row * (GP * 2) + col * 2);
            }
#pragma unroll
            for (int mt = 0; mt < 2; mt++)
#pragma unroll
                for (int nt = 0; nt < 8; nt++)
                    mma_f16h(acc[mt][nt], a[mt],
                             bh[nt >> 1][(nt & 1) * 2], bh[nt >> 1][(nt & 1) * 2 + 1]);
        }
        __syncthreads();
        if (c + 2 < nc) {
            load_chunk_g(Af, Wf, K, bm, bn, (c + 2) * 32,
                         sb + (uint32_t)(((c + 2) % 3) * GSTAGE), tid);
            CP_COMMIT();
        }
    }

    // epilogue
#pragma unroll
    for (int mt = 0; mt < 2; mt++)
#pragma unroll
        for (int nt = 0; nt < 8; nt++) {
            int m0 = bm + wm + mt * 16 + (lane >> 2);
            int n  = bn + wn + nt * 8 + ((lane & 3) << 1);
            size_t i0 = (size_t)m0 * Ntot + n;
            size_t i1 = (size_t)(m0 + 8) * Ntot + n;
            if (Ch) {
                *(__half2*)(Ch + i0) = __floats2half2_rn(acc[mt][nt][0], acc[mt][nt][1]);
                *(__half2*)(Ch + i1) = __floats2half2_rn(acc[mt][nt][2], acc[mt][nt][3]);
            } else {
                float2 v0 = make_float2(acc[mt][nt][0], acc[mt][nt][1]);
                float2 v1 = make_float2(acc[mt][nt][2], acc[mt][nt][3]);
                if (res) {
                    float2 r0 = *(const float2*)(res + i0);
                    float2 r1 = *(const float2*)(res + i1);
                    v0.x += r0.x; v0.y += r0.y;
                    v1.x += r1.x; v1.y += r1.y;
                }
                *(float2*)(Cf + i0) = v0;
                *(float2*)(Cf + i1) = v1;
            }
        }
}

// ================= tensor-core flash attention (f16) =================
// Grid (T/128, H, B), 256 threads = 8 warps; warp owns 16 query rows.
// Q pre-scaled by 1/8 (folded into Wq).
#define QP 72     // Q/K/V smem stride (halves)
#define PP 136    // P smem stride (halves)
#define SQ_OFF 0
#define SK_OFF 9216
#define SV_OFF 18432
#define SP_OFF 27648
#define SP_END (27648 + 128 * PP)
#define BIAS_BYTE (SP_END * 2)
#define SBIAS_BYTE (BIAS_BYTE + 4096 * 4)
#define MW_BYTE (SBIAS_BYTE + 32 * 4)
#define ATT_SMEM (MW_BYTE + 512 * 4)

__global__ void __launch_bounds__(256, 1) attn_tc_kernel(
    const __half* __restrict__ qf, const __half* __restrict__ kf,
    const __half* __restrict__ vf, const uint32_t* __restrict__ mbits,
    const float* __restrict__ relb, const int* __restrict__ btab,
    __half* __restrict__ of)
{
    extern __shared__ char asmem[];
    uint32_t sb = smem_u32(asmem);
    float* biasAll = (float*)(asmem + BIAS_BYTE);
    float* sBias   = (float*)(asmem + SBIAS_BYTE);
    uint32_t* mwp  = (uint32_t*)(asmem + MW_BYTE);

    int qt = blockIdx.x, h = blockIdx.y, b = blockIdx.z;
    int tid = threadIdx.x;
    int lane = tid & 31, w = tid >> 5;
    int i0 = qt * 128;

    if (tid < 32) sBias[tid] = relb[tid * HH + h];
    __syncthreads();
    for (int u = tid; u < 4095; u += 256) biasAll[u] = sBias[btab[u]];

    size_t qbase = ((size_t)b * TT + i0) * DD + h * 64;
#pragma unroll
    for (int i = 0; i < 4; i++) {
        int c = tid + 256 * i;
        int r = c >> 3, cg = c & 7;
        CP_ASYNC16(sb + (uint32_t)((SQ_OFF + r * QP + cg * 8) * 2),
                   (const char*)(qf + qbase + (size_t)r * DD + cg * 8));
    }
    CP_COMMIT(); CP_WAIT(0);
    __syncthreads();

    uint32_t aq[4][4];
#pragma unroll
    for (int ks = 0; ks < 4; ks++) {
        uint32_t row = (uint32_t)(w * 16 + (lane & 15));
        uint32_t col = (uint32_t)(ks * 16 + ((lane >> 4) << 3));
        ldsm_x4(aq[ks], sb + (SQ_OFF + row * QP + col) * 2);
    }

    float o[8][4];
#pragma unroll
    for (int nt = 0; nt < 8; nt++)
#pragma unroll
        for (int e = 0; e < 4; e++) o[nt][e] = 0.f;
    float m0p = -1e30f, m1p = -1e30f, l0 = 0.f, l1 = 0.f;
    int rl0 = w * 16 + (lane >> 2);

    for (int kt = 0; kt < TT / 128; kt++) {
        int j0 = kt * 128;
        size_t kvbase = ((size_t)b * TT + j0) * DD + h * 64;
#pragma unroll
        for (int i = 0; i < 8; i++) {
            int c = tid + 256 * i;
            int buf = c >> 10, r = (c >> 3) & 127, cg = c & 7;
            const __half* srcp = (buf ? vf : kf) + kvbase + (size_t)r * DD + cg * 8;
            uint32_t dst = sb + (uint32_t)(((buf ? SV_OFF : SK_OFF) + r * QP + cg * 8) * 2);
            CP_ASYNC16(dst, (const char*)srcp);
        }
        CP_COMMIT();
#pragma unroll
        for (int i = 0; i < 2; i++) {
            int idx = tid + 256 * i;
            int r = idx >> 2, ws = idx & 3;
            mwp[idx] = mbits[(size_t)(b * TT + i0 + r) * 64 + (j0 >> 5) + ws];
        }
        CP_WAIT(0);
        __syncthreads();

        // S = Q K^T
        float s[16][4];
#pragma unroll
        for (int t = 0; t < 16; t++)
#pragma unroll
            for (int e = 0; e < 4; e++) s[t][e] = 0.f;
#pragma unroll
        for (int ks = 0; ks < 4; ks++) {
#pragma unroll
            for (int g = 0; g < 8; g++) {
                uint32_t grp = (uint32_t)(lane >> 3);
                uint32_t row = (uint32_t)(g * 16) + ((grp >> 1) << 3) + (uint32_t)(lane & 7);
                uint32_t col = (uint32_t)(ks * 16) + ((grp & 1) << 3);
                uint32_t bk[4];
                ldsm_x4(bk, sb + (SK_OFF + row * QP + col) * 2);
                mma_f16h(s[g * 2 + 0], aq[ks], bk[0], bk[1]);
                mma_f16h(s[g * 2 + 1], aq[ks], bk[2], bk[3]);
            }
        }

        // bias + mask
        int ub = 2047 + j0 - i0;
        uint32_t mA[4], mB[4];
#pragma unroll
        for (int k2 = 0; k2 < 4; k2++) {
            mA[k2] = mwp[rl0 * 4 + k2];
            mB[k2] = mwp[(rl0 + 8) * 4 + k2];
        }
#pragma unroll
        for (int t = 0; t < 16; t++) {
            int cjb = t * 8 + ((lane & 3) << 1);
#pragma unroll
            for (int e = 0; e < 4; e++) {
                int cj = cjb + (e & 1);
                int rl = (e < 2) ? rl0 : rl0 + 8;
                float val = s[t][e] + biasAll[ub + cj - rl];
                uint32_t mv = ((e < 2) ? mA : mB)[cj >> 5];
                s[t][e] = ((mv >> (cj & 31)) & 1u) ? val : -1e9f;
            }
        }

        // online softmax (warp-local rows)
        float mx0 = -1e30f, mx1 = -1e30f;
#pragma unroll
        for (int t = 0; t < 16; t++) {
            mx0 = fmaxf(mx0, fmaxf(s[t][0], s[t][1]));
            mx1 = fmaxf(mx1, fmaxf(s[t][2], s[t][3]));
        }
        mx0 = fmaxf(mx0, __shfl_xor_sync(0xffffffffu, mx0, 1));
        mx0 = fmaxf(mx0, __shfl_xor_sync(0xffffffffu, mx0, 2));
        mx1 = fmaxf(mx1, __shfl_xor_sync(0xffffffffu, mx1, 1));
        mx1 = fmaxf(mx1, __shfl_xor_sync(0xffffffffu, mx1, 2));
        float mn0 = fmaxf(m0p, mx0), mn1 = fmaxf(m1p, mx1);
        float corr0 = __expf(m0p - mn0), corr1 = __expf(m1p - mn1);
        float sm0 = 0.f, sm1 = 0.f;
#pragma unroll
        for (int t = 0; t < 16; t++) {
            float p0 = __expf(s[t][0] - mn0);
            float p1 = __expf(s[t][1] - mn0);
            float p2 = __expf(s[t][2] - mn1);
            float p3 = __expf(s[t][3] - mn1);
            sm0 += p0 + p1; sm1 += p2 + p3;
            int cb = t * 8 + ((lane & 3) << 1);
            *(__half2*)(asmem + (SP_OFF + rl0 * PP + cb) * 2)       = __floats2half2_rn(p0, p1);
            *(__half2*)(asmem + (SP_OFF + (rl0 + 8) * PP + cb) * 2) = __floats2half2_rn(p2, p3);
        }
        sm0 += __shfl_xor_sync(0xffffffffu, sm0, 1);
        sm0 += __shfl_xor_sync(0xffffffffu, sm0, 2);
        sm1 += __shfl_xor_sync(0xffffffffu, sm1, 1);
        sm1 += __shfl_xor_sync(0xffffffffu, sm1, 2);
        l0 = l0 * corr0 + sm0;
        l1 = l1 * corr1 + sm1;
        m0p = mn0; m1p = mn1;
#pragma unroll
        for (int nt = 0; nt < 8; nt++) {
            o[nt][0] *= corr0; o[nt][1] *= corr0;
            o[nt][2] *= corr1; o[nt][3] *= corr1;
        }
        __syncwarp();

        // O += P V
#pragma unroll
        for (int ks = 0; ks < 8; ks++) {
            uint32_t ap[4];
            {
                uint32_t row = (uint32_t)(w * 16 + (lane & 15));
                uint32_t col = (uint32_t)(ks * 16 + ((lane >> 4) << 3));
                ldsm_x4(ap, sb + (SP_OFF + row * PP + col) * 2);
            }
#pragma unroll
            for (int g = 0; g < 4; g++) {
                uint32_t row = (uint32_t)(ks * 16 + (lane & 15));
                uint32_t col = (uint32_t)(g * 16 + ((lane >> 4) << 3));
                uint32_t bv[4];
                ldsm_x4_t(bv, sb + (SV_OFF + row * QP + col) * 2);
                mma_f16h(o[g * 2 + 0], ap, bv[0], bv[1]);
                mma_f16h(o[g * 2 + 1], ap, bv[2], bv[3]);
            }
        }
        __syncthreads();
    }

    // epilogue
    float il0 = 1.f / l0, il1 = 1.f / l1;
    size_t r0g = ((size_t)b * TT + i0 + rl0) * DD + h * 64;
    size_t r1g = r0g + (size_t)8 * DD;
#pragma unroll
    for (int nt = 0; nt < 8; nt++) {
        int col = nt * 8 + ((lane & 3) << 1);
        *(__half2*)(of + r0g + col) = __floats2half2_rn(o[nt][0] * il0, o[nt][1] * il0);
        *(__half2*)(of + r1g + col) = __floats2half2_rn(o[nt][2] * il1, o[nt][3] * il1);
    }
}

// ---------------- launch ----------------
extern "C" void kernel_launch(void* const* d_in, const int* in_sizes, int n_in,
                              void* d_out, int out_size) {
    const float* x     = (const float*)d_in[0];
    const int*   xmask = (const int*)d_in[1];
    const float* n1w   = (const float*)d_in[3];
    const float* n3w   = (const float*)d_in[4];
    const float* wqW   = (const float*)d_in[5];
    const float* wqA   = (const float*)d_in[6];
    const float* wqB   = (const float*)d_in[7];
    const float* wkW   = (const float*)d_in[8];
    const float* wvW   = (const float*)d_in[9];
    const float* wvA   = (const float*)d_in[10];
    const float* wvB   = (const float*)d_in[11];
    const float* fcW   = (const float*)d_in[12];
    const float* fcA   = (const float*)d_in[13];
    const float* fcB   = (const float*)d_in[14];
    const float* relb  = (const float*)d_in[15];
    const float* w1W   = (const float*)d_in[16];
    const float* w1A   = (const float*)d_in[17];
    const float* w1B   = (const float*)d_in[18];
    const float* w2W   = (const float*)d_in[19];
    const float* w2A   = (const float*)d_in[20];
    const float* w2B   = (const float*)d_in[21];

    float* scratch = nullptr;
    int* btab = nullptr;
    uint32_t* mbits = nullptr;
    cudaGetSymbolAddress((void**)&scratch, g_scratch);
    cudaGetSymbolAddress((void**)&btab, g_btab);
    cudaGetSymbolAddress((void**)&mbits, g_mbits);

    __half* qfp  = (__half*)(scratch + OFF_QF);
    __half* kfp  = (__half*)(scratch + OFF_KF);
    __half* vfp  = (__half*)(scratch + OFF_VF);
    __half* ofp  = (__half*)(scratch + OFF_OF);
    __half* yf   = (__half*)(scratch + OFF_YF);
    __half* y3f  = (__half*)(scratch + OFF_Y3F);
    __half* ygf  = (__half*)(scratch + OFF_YGF);
    float*  x1   = scratch + OFF_X1;
    __half* h4f  = (__half*)(scratch + OFF_H4F);
    __half* wq   = (__half*)(scratch + OFF_WQ);
    __half* wk   = (__half*)(scratch + OFF_WK);
    __half* wv   = (__half*)(scratch + OFF_WV);
    __half* wfc  = (__half*)(scratch + OFF_WFC);
    __half* w1   = (__half*)(scratch + OFF_W1);
    __half* w2   = (__half*)(scratch + OFF_W2);

    float* out_x    = (float*)d_out;
    float* out_bias = out_x + (size_t)MM * DD;

    cudaFuncSetAttribute(gemm_f16_kernel, cudaFuncAttributeMaxDynamicSharedMemorySize, GEMM_SMEM);
    cudaFuncSetAttribute(attn_tc_kernel, cudaFuncAttributeMaxDynamicSharedMemorySize, ATT_SMEM);

    // 1) tables + big bias output + mask bits
    bucket_kernel<<<(4095 + 255) / 256, 256>>>(btab);
    posbias4_kernel<<<(HH * TT * TT / 4) / 256, 256>>>(relb, btab, (float4*)out_bias);
    maskbits_kernel<<<(BB * TT * 64) / 256, 256>>>(xmask, mbits);

    // 2) weights -> f16 (q gets 0.125 scale folded in)
    merge_f16_kernel<<<(DD * DD) / 256, 256>>>(wqW, wqA, wqB, wq, DD, DD, 0.125f);
    merge_f16_kernel<<<(DD * DD) / 256, 256>>>(wvW, wvA, wvB, wv, DD, DD, 1.0f);
    merge_f16_kernel<<<(DD * DD) / 256, 256>>>(fcW, fcA, fcB, wfc, DD, DD, 1.0f);
    merge_f16_kernel<<<(4 * DD * DD) / 256, 256>>>(w1W, w1A, w1B, w1, 4 * DD, DD, 1.0f);
    merge_f16_kernel<<<(2 * DD * DD) / 256, 256>>>(w2W, w2A, w2B, w2, DD, 2 * DD, 1.0f);
    convert_f16_kernel<<<(DD * DD) / 256, 256>>>(wkW, wk, DD * DD);

    // 3) attention block
    rmsnorm_f16_kernel<<<MM, 256>>>(x, n1w, yf);
    {
        dim3 g(DD / 128, MM / 128);
        gemm_f16_kernel<<<g, 256, GEMM_SMEM>>>(yf, wq, nullptr, nullptr, qfp, MM, DD, DD);
        gemm_f16_kernel<<<g, 256, GEMM_SMEM>>>(yf, wk, nullptr, nullptr, kfp, MM, DD, DD);
        gemm_f16_kernel<<<g, 256, GEMM_SMEM>>>(yf, wv, nullptr, nullptr, vfp, MM, DD, DD);
    }
    {
        dim3 g(TT / 128, HH, BB);
        attn_tc_kernel<<<g, 256, ATT_SMEM>>>(qfp, kfp, vfp, mbits, relb, btab, ofp);
    }
    {
        dim3 g(DD / 128, MM / 128);
        gemm_f16_kernel<<<g, 256, GEMM_SMEM>>>(ofp, wfc, x, x1, nullptr, MM, DD, DD);
    }

    // 4) GEGLU MLP
    rmsnorm_f16_kernel<<<MM, 256>>>(x1, n3w, y3f);
    {
        dim3 g(4 * DD / 128, MM / 128);
        gemm_f16_kernel<<<g, 256, GEMM_SMEM>>>(y3f, w1, nullptr, nullptr, h4f, MM, 4 * DD, DD);
    }
    geglu_f16_kernel<<<(MM * 2048) / 256, 256>>>(h4f, ygf);
    {
        dim3 g(DD / 128, MM / 128);
        gemm_f16_kernel<<<g, 256, GEMM_SMEM>>>(ygf, w2, x1, out_x, nullptr, MM, DD, 2 * DD);
    }
}

// round 13
// speedup vs baseline: 5.2140x; 1.0743x over previous
#include <cuda_runtime.h>
#include <cuda_fp16.h>
#include <math.h>
#include <stdint.h>

// Problem constants
#define BB 2
#define TT 2048
#define DD 1024
#define HH 16
#define DH 64
#define MM (BB*TT)   // 4096 rows
#define QS 3072      // fused qkv row stride (halves)

// ---------------- scratch layout (float units) ----------------
#define OFF_QKV  0u          // f16 [MM][3072]
#define OFF_OF   6291456u    // f16 [MM][DD]
#define OFF_YF   8388608u
#define OFF_Y3F  10485760u
#define OFF_YGF  12582912u   // f16 [MM][2048]
#define OFF_X1   16777216u   // f32 [MM][DD]
#define OFF_H4F  20971520u   // f16 [MM][4096]
#define OFF_WQKV 29360128u   // f16 [3072][1024]
#define OFF_WFC  30932992u   // f16 [1024][1024]
#define OFF_W1   31457280u   // f16 [4096][1024]
#define OFF_W2   33554432u   // f16 [1024][2048]
#define SCRATCH_TOTAL 34603008u

__device__ float    g_scratch[SCRATCH_TOTAL];
__device__ int      g_btab[4095];
__device__ uint32_t g_mbits[BB * TT * 64];

// ================= portable PTX helpers =================
__device__ __forceinline__ uint32_t smem_u32(const void* p) {
    uint32_t a;
    asm("{ .reg .u64 t; cvta.to.shared.u64 t, %1; cvt.u32.u64 %0, t; }"
        : "=r"(a) : "l"(p));
    return a;
}

#define CP_ASYNC16(s, g) \
    asm volatile("cp.async.cg.shared.global [%0], [%1], 16;" :: "r"(s), "l"(g))
#define CP_COMMIT() asm volatile("cp.async.commit_group;")
#define CP_WAIT(n)  asm volatile("cp.async.wait_group %0;" :: "n"(n))

__device__ __forceinline__ void ldsm_x4(uint32_t* d, uint32_t a) {
    asm volatile("ldmatrix.sync.aligned.m8n8.x4.shared.b16 {%0,%1,%2,%3}, [%4];"
        : "=r"(d[0]), "=r"(d[1]), "=r"(d[2]), "=r"(d[3]) : "r"(a));
}
__device__ __forceinline__ void ldsm_x4_t(uint32_t* d, uint32_t a) {
    asm volatile("ldmatrix.sync.aligned.m8n8.x4.trans.shared.b16 {%0,%1,%2,%3}, [%4];"
        : "=r"(d[0]), "=r"(d[1]), "=r"(d[2]), "=r"(d[3]) : "r"(a));
}

__device__ __forceinline__ void mma_f16h(float* c, const uint32_t* a,
                                         uint32_t b0, uint32_t b1) {
    asm volatile(
        "mma.sync.aligned.m16n8k16.row.col.f32.f16.f16.f32 "
        "{%0,%1,%2,%3}, {%4,%5,%6,%7}, {%8,%9}, {%0,%1,%2,%3};"
        : "+f"(c[0]), "+f"(c[1]), "+f"(c[2]), "+f"(c[3])
        : "r"(a[0]), "r"(a[1]), "r"(a[2]), "r"(a[3]), "r"(b0), "r"(b1));
}

// ---------------- T5 relative bucket table ----------------
__global__ void bucket_kernel(int* btab) {
    int idx = blockIdx.x * 256 + threadIdx.x;
    if (idx >= 4095) return;
    int rel = idx - 2047;
    int b = (rel > 0) ? 16 : 0;
    int a = rel < 0 ? -rel : rel;
    if (a < 8) {
        b += a;
    } else {
        int large;
        if ((a & (a - 1)) == 0) {
            int e = 31 - __clz(a);
            large = 8 + 2 * (e - 3);
        } else {
            large = 8 + (int)(2.0 * (log2((double)a) - 3.0));
        }
        b += (large < 15) ? large : 15;
    }
    btab[idx] = b;
}

// ---------------- pos_bias output: [H, T, T], float4 vectorized ----------------
__global__ void posbias4_kernel(const float* __restrict__ relb,
                                const int* __restrict__ btab,
                                float4* __restrict__ out) {
    int idx = blockIdx.x * 256 + threadIdx.x;
    if (idx >= HH * TT * TT / 4) return;
    int h = idx >> 20;
    int r = idx & 1048575;
    int i = r >> 9;
    int j4 = (r & 511) << 2;
    int base = j4 - i + 2047;
    float4 v;
    v.x = relb[btab[base + 0] * HH + h];
    v.y = relb[btab[base + 1] * HH + h];
    v.z = relb[btab[base + 2] * HH + h];
    v.w = relb[btab[base + 3] * HH + h];
    out[idx] = v;
}

// ---------------- pack mask to bits ----------------
__global__ void maskbits_kernel(const int* __restrict__ xmask,
                                uint32_t* __restrict__ mbits) {
    int idx = blockIdx.x * 256 + threadIdx.x;
    if (idx >= BB * TT * 64) return;
    int w = idx & 63;
    int bi = idx >> 6;
    const int* src = xmask + (size_t)bi * TT + w * 32;
    uint32_t bits = 0;
#pragma unroll
    for (int j = 0; j < 32; j++) bits |= (src[j] != 0 ? 1u : 0u) << j;
    mbits[idx] = bits;
}

// ---------------- LoRA merge -> f16 (single, with scale) ----------------
__global__ void merge_f16_kernel(const float* __restrict__ W,
                                 const float* __restrict__ A,
                                 const float* __restrict__ Bm,
                                 __half* __restrict__ out, int N, int K,
                                 float scale) {
    int idx = blockIdx.x * 256 + threadIdx.x;
    if (idx >= N * K) return;
    int n = idx / K, kk = idx - n * K;
    float s = 0.f;
#pragma unroll
    for (int r = 0; r < 8; r++) s += Bm[n * 8 + r] * A[r * K + kk];
    out[idx] = __float2half((W[idx] + 0.125f * s) * scale);
}

// ---------------- f32 -> f16 ----------------
__global__ void convert_f16_kernel(const float* __restrict__ in,
                                   __half* __restrict__ out, int n) {
    int idx = blockIdx.x * 256 + threadIdx.x;
    if (idx < n) out[idx] = __float2half(in[idx]);
}

// ---------------- RMSNorm -> f16 ----------------
__global__ void rmsnorm_f16_kernel(const float* __restrict__ x,
                                   const float* __restrict__ w,
                                   __half* __restrict__ y) {
    int row = blockIdx.x;
    const float* xp = x + (size_t)row * DD;
    float ss = 0.f;
    for (int d = threadIdx.x; d < DD; d += 256) { float v = xp[d]; ss += v * v; }
    __shared__ float red[256];
    red[threadIdx.x] = ss;
    __syncthreads();
    for (int s = 128; s > 0; s >>= 1) {
        if (threadIdx.x < s) red[threadIdx.x] += red[threadIdx.x + s];
        __syncthreads();
    }
    float inv = rsqrtf(red[0] * (1.0f / DD) + 1e-6f);
    for (int d = threadIdx.x; d < DD; d += 256)
        y[(size_t)row * DD + d] = __float2half(w[d] * xp[d] * inv);
}

// ---------------- GEGLU (f16 in) -> f16 ----------------
__global__ void geglu_f16_kernel(const __half* __restrict__ h,
                                 __half* __restrict__ yg) {
    int idx = blockIdx.x * 256 + threadIdx.x;
    if (idx >= MM * 2048) return;
    int m = idx >> 11, c = idx & 2047;
    float p1 = __half2float(h[(size_t)m * 4096 + c]);
    float p2 = __half2float(h[(size_t)m * 4096 + 2048 + c]);
    float u = 0.7978845608f * (p2 + 0.044715f * p2 * p2 * p2);
    float g = 0.5f * p2 * (1.f + tanhf(u));
    yg[idx] = __float2half(p1 * g);
}

// ================= mma.sync f16 GEMM (4-stage pipeline, 1 barrier/chunk) =================
// C[M,N] = A[M,K] @ W[N,K]^T  (+res f32 -> f32 out, or f16 out)
#define GP      40
#define GBUF    (128 * GP * 2)    // 10240 B
#define GSTAGE  (2 * GBUF)        // A, W = 20480 B
#define GEMM_SMEM (4 * GSTAGE)    // 81920 B

__device__ __forceinline__ void load_chunk_g(
    const __half* Af, const __half* Wf, int K,
    int bm, int bn, int k0, uint32_t sstage, int tid)
{
#pragma unroll
    for (int i = 0; i < 4; i++) {
        int idx = tid + 256 * i;
        int buf = idx >> 9;
        int rem = idx & 511;
        int r = rem >> 2, cg = rem & 3;
        const __half* src = buf ? (Wf + (size_t)(bn + r) * K + k0 + cg * 8)
                                : (Af + (size_t)(bm + r) * K + k0 + cg * 8);
        CP_ASYNC16(sstage + (uint32_t)(buf * GBUF + r * (GP * 2) + cg * 16),
                   (const char*)src);
    }
}

__global__ void __launch_bounds__(256, 1) gemm_f16_kernel(
    const __half* __restrict__ Af, const __half* __restrict__ Wf,
    const float* __restrict__ res, float* __restrict__ Cf,
    __half* __restrict__ Ch,
    int Mtot, int Ntot, int K)
{
    extern __shared__ char gsm[];
    uint32_t sb = smem_u32(gsm);
    int tid = threadIdx.x;
    int lane = tid & 31, w = tid >> 5;
    int wm = (w & 3) * 32, wn = (w >> 2) * 64;
    int bm = blockIdx.y * 128, bn = blockIdx.x * 128;

    float acc[2][8][4];
#pragma unroll
    for (int mt = 0; mt < 2; mt++)
#pragma unroll
        for (int nt = 0; nt < 8; nt++)
#pragma unroll
            for (int e = 0; e < 4; e++) acc[mt][nt][e] = 0.f;

    int nc = K / 32;
    load_chunk_g(Af, Wf, K, bm, bn, 0, sb, tid);           CP_COMMIT();
    load_chunk_g(Af, Wf, K, bm, bn, 32, sb + GSTAGE, tid); CP_COMMIT();
    load_chunk_g(Af, Wf, K, bm, bn, 64, sb + 2 * GSTAGE, tid); CP_COMMIT();

    for (int c = 0; c < nc; c++) {
        // wait so that exactly chunk c is guaranteed complete
        if (c + 3 <= nc)      { CP_WAIT(2); }
        else if (c + 2 <= nc) { CP_WAIT(1); }
        else                  { CP_WAIT(0); }
        __syncthreads();
        // prefetch chunk c+3: its buffer (c-1)%4 was fully consumed at iter c-1,
        // and every thread is past this barrier => safe. No end-of-iter barrier.
        if (c + 3 < nc) {
            load_chunk_g(Af, Wf, K, bm, bn, (c + 3) * 32,
                         sb + (uint32_t)(((c + 3) & 3) * GSTAGE), tid);
            CP_COMMIT();
        }
        uint32_t st = sb + (uint32_t)((c & 3) * GSTAGE);
#pragma unroll
        for (int ks = 0; ks < 2; ks++) {
            int k0 = ks * 16;
            uint32_t a[2][4], bh[4][4];
#pragma unroll
            for (int mt = 0; mt < 2; mt++) {
                uint32_t row = (uint32_t)(wm + mt * 16 + (lane & 15));
                uint32_t col = (uint32_t)(k0 + ((lane >> 4) << 3));
                ldsm_x4(a[mt], st + row * (GP * 2) + col * 2);
            }
#pragma unroll
            for (int g = 0; g < 4; g++) {
                uint32_t grp = (uint32_t)(lane >> 3);
                uint32_t row = (uint32_t)(wn + g * 16) + ((grp >> 1) << 3) + (uint32_t)(lane & 7);
                uint32_t col = (uint32_t)k0 + ((grp & 1) << 3);
                ldsm_x4(bh[g], st + GBUF + row * (GP * 2) + col * 2);
            }
#pragma unroll
            for (int mt = 0; mt < 2; mt++)
#pragma unroll
                for (int nt = 0; nt < 8; nt++)
                    mma_f16h(acc[mt][nt], a[mt],
                             bh[nt >> 1][(nt & 1) * 2], bh[nt >> 1][(nt & 1) * 2 + 1]);
        }
    }

    // epilogue
#pragma unroll
    for (int mt = 0; mt < 2; mt++)
#pragma unroll
        for (int nt = 0; nt < 8; nt++) {
            int m0 = bm + wm + mt * 16 + (lane >> 2);
            int n  = bn + wn + nt * 8 + ((lane & 3) << 1);
            size_t i0 = (size_t)m0 * Ntot + n;
            size_t i1 = (size_t)(m0 + 8) * Ntot + n;
            if (Ch) {
                *(__half2*)(Ch + i0) = __floats2half2_rn(acc[mt][nt][0], acc[mt][nt][1]);
                *(__half2*)(Ch + i1) = __floats2half2_rn(acc[mt][nt][2], acc[mt][nt][3]);
            } else {
                float2 v0 = make_float2(acc[mt][nt][0], acc[mt][nt][1]);
                float2 v1 = make_float2(acc[mt][nt][2], acc[mt][nt][3]);
                if (res) {
                    float2 r0 = *(const float2*)(res + i0);
                    float2 r1 = *(const float2*)(res + i1);
                    v0.x += r0.x; v0.y += r0.y;
                    v1.x += r1.x; v1.y += r1.y;
                }
                *(float2*)(Cf + i0) = v0;
                *(float2*)(Cf + i1) = v1;
            }
        }
}

// ================= tensor-core flash attention (f16, double-buffered K/V) =================
// Grid (T/128, H, B), 256 threads = 8 warps; warp owns 16 query rows.
// Q pre-scaled by 1/8 (folded into Wq). q/k/v interleaved with row stride QS.
#define QP 72
#define PP 136
#define SQ_OFF 0
// K/V parity buffers
#define SKV0 9216
#define SKV1 27648
#define SKVSZ 9216     // each of K,V = 128*72 halves
#define SP_OFF 46080
#define SP_END (46080 + 128 * PP)          // 63488 halves
#define BIAS_BYTE (SP_END * 2)             // 126976
#define SBIAS_BYTE (BIAS_BYTE + 4096 * 4)  // 143360
#define MW_BYTE (SBIAS_BYTE + 32 * 4)      // 143488
#define ATT_SMEM (MW_BYTE + 1024 * 4)      // 147584

__global__ void __launch_bounds__(256, 1) attn_tc_kernel(
    const __half* __restrict__ qkv, const uint32_t* __restrict__ mbits,
    const float* __restrict__ relb, const int* __restrict__ btab,
    __half* __restrict__ of)
{
    extern __shared__ char asmem[];
    uint32_t sb = smem_u32(asmem);
    float* biasAll = (float*)(asmem + BIAS_BYTE);
    float* sBias   = (float*)(asmem + SBIAS_BYTE);
    uint32_t* mwp  = (uint32_t*)(asmem + MW_BYTE);   // [2][512]

    int qt = blockIdx.x, h = blockIdx.y, b = blockIdx.z;
    int tid = threadIdx.x;
    int lane = tid & 31, w = tid >> 5;
    int i0 = qt * 128;

    if (tid < 32) sBias[tid] = relb[tid * HH + h];
    for (int u = tid; u < 4095; u += 256) {
        // sBias written by warp 0; other threads read via btab -> need it visible.
        // warp 0 wrote before this loop only for its own threads; use relb directly.
        biasAll[u] = relb[btab[u] * HH + h];
    }

    const __half* qf = qkv + h * 64;
    const __half* kf = qkv + 1024 + h * 64;
    const __half* vf = qkv + 2048 + h * 64;

    // prologue: Q tile + KV tile 0 + mask 0
    size_t qbase = (size_t)(b * TT + i0) * QS;
#pragma unroll
    for (int i = 0; i < 4; i++) {
        int c = tid + 256 * i;
        int r = c >> 3, cg = c & 7;
        CP_ASYNC16(sb + (uint32_t)((SQ_OFF + r * QP + cg * 8) * 2),
                   (const char*)(qf + qbase + (size_t)r * QS + cg * 8));
    }
    size_t kvbase0 = (size_t)(b * TT) * QS;
#pragma unroll
    for (int i = 0; i < 8; i++) {
        int c = tid + 256 * i;
        int buf = c >> 10, r = (c >> 3) & 127, cg = c & 7;
        const __half* srcp = (buf ? vf : kf) + kvbase0 + (size_t)r * QS + cg * 8;
        CP_ASYNC16(sb + (uint32_t)((SKV0 + buf * SKVSZ + r * QP + cg * 8) * 2),
                   (const char*)srcp);
    }
    CP_COMMIT();
#pragma uroll
    for (int i = 0; i < 2; i++) {
        int idx = tid + 256 * i;
        int r = idx >> 2, ws = idx & 3;
        mwp[idx] = mbits[(size_t)(b * TT + i0 + r) * 64 + ws];
    }
    CP_WAIT(0);
    __syncthreads();

    uint32_t aq[4][4];
#pragma unroll
    for (int ks = 0; ks < 4; ks++) {
        uint32_t row = (uint32_t)(w * 16 + (lane & 15));
        uint32_t col = (uint32_t)(ks * 16 + ((lane >> 4) << 3));
        ldsm_x4(aq[ks], sb + (SQ_OFF + row * QP + col) * 2);
    }

    float o[8][4];
#pragma unroll
    for (int nt = 0; nt < 8; nt++)
#pragma unroll
        for (int e = 0; e < 4; e++) o[nt][e] = 0.f;
    float m0p = -1e30f, m1p = -1e30f, l0 = 0.f, l1 = 0.f;
    int rl0 = w * 16 + (lane >> 2);

    const int NT = TT / 128;
    for (int kt = 0; kt < NT; kt++) {
        // tile kt was prefetched during iter kt-1 (or prologue)
        CP_WAIT(0);
        __syncthreads();   // all warps done with iter kt-1; kt data visible everywhere

        // prefetch tile kt+1 into the other parity (its last reader was iter kt-1)
        if (kt + 1 < NT) {
            size_t kvb = (size_t)(b * TT + (kt + 1) * 128) * QS;
            uint32_t dstb = (uint32_t)(((kt + 1) & 1) ? SKV1 : SKV0);
#pragma unroll
            for (int i = 0; i < 8; i++) {
                int c = tid + 256 * i;
                int buf = c >> 10, r = (c >> 3) & 127, cg = c & 7;
                const __half* srcp = (buf ? vf : kf) + kvb + (size_t)r * QS + cg * 8;
                CP_ASYNC16(sb + (uint32_t)((dstb + buf * SKVSZ + r * QP + cg * 8) * 2),
                           (const char*)srcp);
            }
            CP_COMMIT();
#pragma unroll
            for (int i = 0; i < 2; i++) {
                int idx = tid + 256 * i;
                int r = idx >> 2, ws = idx & 3;
                mwp[((kt + 1) & 1) * 512 + idx] =
                    mbits[(size_t)(b * TT + i0 + r) * 64 + ((kt + 1) * 4) + ws];
            }
        }

        uint32_t skv = (uint32_t)((kt & 1) ? SKV1 : SKV0);
        int j0 = kt * 128;

        // S = Q K^T
        float s[16][4];
#pragma unroll
        for (int t = 0; t < 16; t++)
#pragma unroll
            for (int e = 0; e < 4; e++) s[t][e] = 0.f;
#pragma unroll
        for (int ks = 0; ks < 4; ks++) {
#pragma unroll
            for (int g = 0; g < 8; g++) {
                uint32_t grp = (uint32_t)(lane >> 3);
                uint32_t row = (uint32_t)(g * 16) + ((grp >> 1) << 3) + (uint32_t)(lane & 7);
                uint32_t col = (uint32_t)(ks * 16) + ((grp & 1) << 3);
                uint32_t bk[4];
                ldsm_x4(bk, sb + (skv + row * QP + col) * 2);
                mma_f16h(s[g * 2 + 0], aq[ks], bk[0], bk[1]);
                mma_f16h(s[g * 2 + 1], aq[ks], bk[2], bk[3]);
            }
        }

        // bias + mask
        int ub = 2047 + j0 - i0;
        const uint32_t* mw = mwp + (kt & 1) * 512;
        uint32_t mA[4], mB[4];
#pragma unroll
        for (int k2 = 0; k2 < 4; k2++) {
            mA[k2] = mw[rl0 * 4 + k2];
            mB[k2] = mw[(rl0 + 8) * 4 + k2];
        }
#pragma unroll
        for (int t = 0; t < 16; t++) {
            int cjb = t * 8 + ((lane & 3) << 1);
#pragma unroll
            for (int e = 0; e < 4; e++) {
                int cj = cjb + (e & 1);
                int rl = (e < 2) ? rl0 : rl0 + 8;
                float val = s[t][e] + biasAll[ub + cj - rl];
                uint32_t mv = ((e < 2) ? mA : mB)[cj >> 5];
                s[t][e] = ((mv >> (cj & 31)) & 1u) ? val : -1e9f;
            }
        }

        // online softmax (warp-local rows)
        float mx0 = -1e30f, mx1 = -1e30f;
#pragma unroll
        for (int t = 0; t < 16; t++) {
            mx0 = fmaxf(mx0, fmaxf(s[t][0], s[t][1]));
            mx1 = fmaxf(mx1, fmaxf(s[t][2], s[t][3]));
        }
        mx0 = fmaxf(mx0, __shfl_xor_sync(0xffffffffu, mx0, 1));
        mx0 = fmaxf(mx0, __shfl_xor_sync(0xffffffffu, mx0, 2));
        mx1 = fmaxf(mx1, __shfl_xor_sync(0xffffffffu, mx1, 1));
        mx1 = fmaxf(mx1, __shfl_xor_sync(0xffffffffu, mx1, 2));
        float mn0 = fmaxf(m0p, mx0), mn1 = fmaxf(m1p, mx1);
        float corr0 = __expf(m0p - mn0), corr1 = __expf(m1p - mn1);
        float sm0 = 0.f, sm1 = 0.f;
#pragma unroll
        for (int t = 0; t < 16; t++) {
            float p0 = __expf(s[t][0] - mn0);
            float p1 = __expf(s[t][1] - mn0);
            float p2 = __expf(s[t][2] - mn1);
            float p3 = __expf(s[t][3] - mn1);
            sm0 += p0 + p1; sm1 += p2 + p3;
            int cb = t * 8 + ((lane & 3) << 1);
            *(__half2*)(asmem + (SP_OFF + rl0 * PP + cb) * 2)       = __floats2half2_rn(p0, p1);
            *(__half2*)(asmem + (SP_OFF + (rl0 + 8) * PP + cb) * 2) = __floats2half2_rn(p2, p3);
        }
        sm0 += __shfl_xor_sync(0xffffffffu, sm0, 1);
        sm0 += __shfl_xor_sync(0xffffffffu, sm0, 2);
        sm1 += __shfl_xor_sync(0xffffffffu, sm1, 1);
        sm1 += __shfl_xor_sync(0xffffffffu, sm1, 2);
        l0 = l0 * corr0 + sm0;
        l1 = l1 * corr1 + sm1;
        m0p = mn0; m1p = mn1;
#pragma unroll
        for (int nt = 0; nt < 8; nt++) {
            o[nt][0] *= corr0; o[nt][1] *= corr0;
            o[nt][2] *= corr1; o[nt][3] *= corr1;
        }
        __syncwarp();

        // O += P V   (P rows are warp-private; V from current parity buffer)
#pragma unroll
        for (int ks = 0; ks < 8; ks++) {
            uint32_t ap[4];
            {
                uint32_t row = (uint32_t)(w * 16 + (lane & 15));
                uint32_t col = (uint32_t)(ks * 16 + ((lane >> 4) << 3));
                ldsm_x4(ap, sb + (SP_OFF + row * PP + col) * 2);
            }
#pragma unroll
            for (int g = 0; g < 4; g++) {
                uint32_t row = (uint32_t)(ks * 16 + (lane & 15));
                uint32_t col = (uint32_t)(g * 16 + ((lane >> 4) << 3));
                uint32_t bv[4];
                ldsm_x4_t(bv, sb + (skv + SKVSZ + row * QP + col) * 2);
                mma_f16h(o[g * 2 + 0], ap, bv[0], bv[1]);
                mma_f16h(o[g * 2 + 1], ap, bv[2], bv[3]);
            }
        }
        // no end-of-iter barrier: next iter's top barrier provides it
    }

    // epilogue
    float il0 = 1.f / l0, il1 = 1.f / l1;
    size_t r0g = ((size_t)b * TT + i0 + rl0) * DD + h * 64;
    size_t r1g = r0g + (size_t)8 * DD;
#pragma unroll
    for (int nt = 0; nt < 8; nt++) {
        int col = nt * 8 + ((lane & 3) << 1);
        *(__half2*)(of + r0g + col) = __floats2half2_rn(o[nt][0] * il0, o[nt][1] * il0);
        *(__half2*)(of + r1g + col) = __floats2half2_rn(o[nt][2] * il1, o[nt][3] * il1);
    }
}

// ---------------- launch ----------------
extern "C" void kernel_launch(void* const* d_in, const int* in_sizes, int n_in,
                              void* d_out, int out_size) {
    const float* x     = (const float*)d_in[0];
    const int*   xmask = (const int*)d_in[1];
    const float* n1w   = (const float*)d_in[3];
    const float* n3w   = (const float*)d_in[4];
    const float* wqW   = (const float*)d_in[5];
    const float* wqA   = (const float*)d_in[6];
    const float* wqB   = (const float*)d_in[7];
    const float* wkW   = (const float*)d_in[8];
    const float* wvW   = (const float*)d_in[9];
    const float* wvA   = (const float*)d_in[10];
    const float* wvB   = (const float*)d_in[11];
    const float* fcW   = (const float*)d_in[12];
    const float* fcA   = (const float*)d_in[13];
    const float* fcB   = (const float*)d_in[14];
    const float* relb  = (const float*)d_in[15];
    const float* w1W   = (const float*)d_in[16];
    const float* w1A   = (const float*)d_in[17];
    const float* w1B   = (const float*)d_in[18];
    const float* w2W   = (const float*)d_in[19];
    const float* w2A   = (const float*)d_in[20];
    const float* w2B   = (const float*)d_in[21];

    float* scratch = nullptr;
    int* btab = nullptr;
    uint32_t* mbits = nullptr;
    cudaGetSymbolAddress((void**)&scratch, g_scratch);
    cudaGetSymbolAddress((void**)&btab, g_btab);
    cudaGetSymbolAddress((void**)&mbits, g_mbits);

    __half* qkvh = (__half*)(scratch + OFF_QKV);
    __half* ofp  = (__half*)(scratch + OFF_OF);
    __half* yf   = (__half*)(scratch + OFF_YF);
    __half* y3f  = (__half*)(scratch + OFF_Y3F);
    __half* ygf  = (__half*)(scratch + OFF_YGF);
    float*  x1   = scratch + OFF_X1;
    __half* h4f  = (__half*)(scratch + OFF_H4F);
    __half* wqkv = (__half*)(scratch + OFF_WQKV);
    __half* wfc  = (__half*)(scratch + OFF_WFC);
    __half* w1   = (__half*)(scratch + OFF_W1);
    __half* w2   = (__half*)(scratch + OFF_W2);

    float* out_x    = (float*)d_out;
    float* out_bias = out_x + (size_t)MM * DD;

    cudaFuncSetAttribute(gemm_f16_kernel, cudaFuncAttributeMaxDynamicSharedMemorySize, GEMM_SMEM);
    cudaFuncSetAttribute(attn_tc_kernel, cudaFuncAttributeMaxDynamicSharedMemorySize, ATT_SMEM);

    // 1) tables + big bias output + mask bits
    bucket_kernel<<<(4095 + 255) / 256, 256>>>(btab);
    posbias4_kernel<<<(HH * TT * TT / 4) / 256, 256>>>(relb, btab, (float4*)out_bias);
    maskbits_kernel<<<(BB * TT * 64) / 256, 256>>>(xmask, mbits);

    // 2) weights -> fused qkv f16 buffer [3072][1024] (q scaled by 1/8), rest
    merge_f16_kernel<<<(DD * DD) / 256, 256>>>(wqW, wqA, wqB, wqkv, DD, DD, 0.125f);
    convert_f16_kernel<<<(DD * DD) / 256, 256>>>(wkW, wqkv + (size_t)DD * DD, DD * DD);
    merge_f16_kernel<<<(DD * DD) / 256, 256>>>(wvW, wvA, wvB, wqkv + (size_t)2 * DD * DD, DD, DD, 1.0f);
    merge_f16_kernel<<<(DD * DD) / 256, 256>>>(fcW, fcA, fcB, wfc, DD, DD, 1.0f);
    merge_f16_kernel<<<(4 * DD * DD) / 256, 256>>>(w1W, w1A, w1B, w1, 4 * DD, DD, 1.0f);
    merge_f16_kernel<<<(2 * DD * DD) / 256, 256>>>(w2W, w2A, w2B, w2, DD, 2 * DD, 1.0f);

    // 3) attention block
    rmsnorm_f16_kernel<<<MM, 256>>>(x, n1w, yf);
    {
        dim3 g(QS / 128, MM / 128);   // (24, 32) fused QKV
        gemm_f16_kernel<<<g, 256, GEMM_SMEM>>>(yf, wqkv, nullptr, nullptr, qkvh, MM, QS, DD);
    }
    {
        dim3 g(TT / 128, HH, BB);
        attn_tc_kernel<<<g, 256, ATT_SMEM>>>(qkvh, mbits, relb, btab, ofp);
    }
    {
        dim3 g(DD / 128, MM / 128);
        gemm_f16_kernel<<<g, 256, GEMM_SMEM>>>(ofp, wfc, x, x1, nullptr, MM, DD, DD);
    }

    // 4) GEGLU MLP
    rmsnorm_f16_kernel<<<MM, 256>>>(x1, n3w, y3f);
    {
        dim3 g(4 * DD / 128, MM / 128);
        gemm_f16_kernel<<<g, 256, GEMM_SMEM>>>(y3f, w1, nullptr, nullptr, h4f, MM, 4 * DD, DD);
    }
    geglu_f16_kernel<<<(MM * 2048) / 256, 256>>>(h4f, ygf);
    {
        dim3 g(DD / 128, MM / 128);
        gemm_f16_kernel<<<g, 256, GEMM_SMEM>>>(ygf, w2, x1, out_x, nullptr, MM, DD, 2 * DD);
    }
}

// round 15
// speedup vs baseline: 5.4869x; 1.0523x over previous
#include <cuda_runtime.h>
#include <cuda_fp16.h>
#include <math.h>
#include <stdint.h>

// Problem constants
#define BB 2
#define TT 2048
#define DD 1024
#define HH 16
#define DH 64
#define MM (BB*TT)   // 4096 rows
#define QS 3072      // fused qkv row stride (halves)

// ---------------- scratch layout (float units) ----------------
#define OFF_QKV  0u          // f16 [MM][3072]
#define OFF_OF   6291456u    // f16 [MM][DD]
#define OFF_YF   8388608u
#define OFF_Y3F  10485760u
#define OFF_YGF  12582912u   // f16 [MM][2048]
#define OFF_X1   16777216u   // f32 [MM][DD]
#define OFF_WQKV 20971520u   // f16 [3072][1024]
#define OFF_WFC  22544384u   // f16 [1024][1024]
#define OFF_W1   23068672u   // f16 [4096][1024] (interleaved rows)
#define OFF_W2   25165824u   // f16 [1024][2048]
#define SCRATCH_TOTAL 26214400u

__device__ float    g_scratch[SCRATCH_TOTAL];
__device__ int      g_btab[4095];
__device__ uint32_t g_mbits[BB * TT * 64];

// ================= portable PTX helpers =================
__device__ __forceinline__ uint32_t smem_u32(const void* p) {
    uint32_t a;
    asm("{ .reg .u64 t; cvta.to.shared.u64 t, %1; cvt.u32.u64 %0, t; }"
        : "=r"(a) : "l"(p));
    return a;
}

#define CP_ASYNC16(s, g) \
    asm volatile("cp.async.cg.shared.global [%0], [%1], 16;" :: "r"(s), "l"(g))
#define CP_COMMIT() asm volatile("cp.async.commit_group;")
#define CP_WAIT(n)  asm volatile("cp.async.wait_group %0;" :: "n"(n))

__device__ __forceinline__ void ldsm_x4(uint32_t* d, uint32_t a) {
    asm volatile("ldmatrix.sync.aligned.m8n8.x4.shared.b16 {%0,%1,%2,%3}, [%4];"
        : "=r"(d[0]), "=r"(d[1]), "=r"(d[2]), "=r"(d[3]) : "r"(a));
}
__device__ __forceinline__ void ldsm_x4_t(uint32_t* d, uint32_t a) {
    asm volatile("ldmatrix.sync.aligned.m8n8.x4.trans.shared.b16 {%0,%1,%2,%3}, [%4];"
        : "=r"(d[0]), "=r"(d[1]), "=r"(d[2]), "=r"(d[3]) : "r"(a));
}

__device__ __forceinline__ void mma_f16h(float* c, const uint32_t* a,
                                         uint32_t b0, uint32_t b1) {
    asm volatile(
        "mma.sync.aligned.m16n8k16.row.col.f32.f16.f16.f32 "
        "{%0,%1,%2,%3}, {%4,%5,%6,%7}, {%8,%9}, {%0,%1,%2,%3};"
        : "+f"(c[0]), "+f"(c[1]), "+f"(c[2]), "+f"(c[3])
        : "r"(a[0]), "r"(a[1]), "r"(a[2]), "r"(a[3]), "r"(b0), "r"(b1));
}

__device__ __forceinline__ float gelu_t(float p2) {
    float u = 0.7978845608f * (p2 + 0.044715f * p2 * p2 * p2);
    return 0.5f * p2 * (1.f + tanhf(u));
}

// ---------------- T5 relative bucket table ----------------
__global__ void bucket_kernel(int* btab) {
    int idx = blockIdx.x * 256 + threadIdx.x;
    if (idx >= 4095) return;
    int rel = idx - 2047;
    int b = (rel > 0) ? 16 : 0;
    int a = rel < 0 ? -rel : rel;
    if (a < 8) {
        b += a;
    } else {
        int large;
        if ((a & (a - 1)) == 0) {
            int e = 31 - __clz(a);
            large = 8 + 2 * (e - 3);
        } else {
            large = 8 + (int)(2.0 * (log2((double)a) - 3.0));
        }
        b += (large < 15) ? large : 15;
    }
    btab[idx] = b;
}

// ---------------- pack mask to bits ----------------
__global__ void maskbits_kernel(const int* __restrict__ xmask,
                                uint32_t* __restrict__ mbits) {
    int idx = blockIdx.x * 256 + threadIdx.x;
    if (idx >= BB * TT * 64) return;
    int w = idx & 63;
    int bi = idx >> 6;
    const int* src = xmask + (size_t)bi * TT + w * 32;
    uint32_t bits = 0;
#pragma unroll
    for (int j = 0; j < 32; j++) bits |= (src[j] != 0 ? 1u : 0u) << j;
    mbits[idx] = bits;
}

// ---------------- LoRA merge -> f16 (single, with scale) ----------------
__global__ void merge_f16_kernel(const float* __restrict__ W,
                                 const float* __restrict__ A,
                                 const float* __restrict__ Bm,
                                 __half* __restrict__ out, int N, int K,
                                 float scale) {
    int idx = blockIdx.x * 256 + threadIdx.x;
    if (idx >= N * K) return;
    int n = idx / K, kk = idx - n * K;
    float s = 0.f;
#pragma unroll
    for (int r = 0; r < 8; r++) s += Bm[n * 8 + r] * A[r * K + kk];
    out[idx] = __float2half((W[idx] + 0.125f * s) * scale);
}

// ---------------- w1 LoRA merge with row interleave ----------------
// new row 2c = old row c (p1), new row 2c+1 = old row 2048+c (p2)
__global__ void merge_w1i_kernel(const float* __restrict__ W,
                                 const float* __restrict__ A,
                                 const float* __restrict__ Bm,
                                 __half* __restrict__ out) {
    int idx = blockIdx.x * 256 + threadIdx.x;
    if (idx >= 4096 * 1024) return;
    int n = idx >> 10, kk = idx & 1023;
    int src = (n & 1) ? (2048 + (n >> 1)) : (n >> 1);
    float s = 0.f;
#pragma unroll
    for (int r = 0; r < 8; r++) s += Bm[src * 8 + r] * A[r * 1024 + kk];
    out[idx] = __float2half(W[src * 1024 + kk] + 0.125f * s);
}

// ---------------- f32 -> f16 ----------------
__global__ void convert_f16_kernel(const float* __restrict__ in,
                                   __half* __restrict__ out, int n) {
    int idx = blockIdx.x * 256 + threadIdx.x;
    if (idx < n) out[idx] = __float2half(in[idx]);
}

// ---------------- RMSNorm -> f16 ----------------
__global__ void rmsnorm_f16_kernel(const float* __restrict__ x,
                                   const float* __restrict__ w,
                                   __half* __restrict__ y) {
    int row = blockIdx.x;
    const float* xp = x + (size_t)row * DD;
    float ss = 0.f;
    for (int d = threadIdx.x; d < DD; d += 256) { float v = xp[d]; ss += v * v; }
    __shared__ float red[256];
    red[threadIdx.x] = ss;
    __syncthreads();
    for (int s = 128; s > 0; s >>= 1) {
        if (threadIdx.x < s) red[threadIdx.x] += red[threadIdx.x + s];
        __syncthreads();
    }
    float inv = rsqrtf(red[0] * (1.0f / DD) + 1e-6f);
    for (int d = threadIdx.x; d < DD; d += 256)
        y[(size_t)row * DD + d] = __float2half(w[d] * xp[d] * inv);
}

// ================= mma.sync f16 GEMM (4-stage pipeline, 1 barrier/chunk) =================
// mode 0: f32 out (+res) ; mode 1: f16 out ; mode 2: geglu f16 out (cols halved)
#define GP      40
#define GBUF    (128 * GP * 2)
#define GSTAGE  (2 * GBUF)
#define GEMM_SMEM (4 * GSTAGE)

__device__ __forceinline__ void load_chunk_g(
    const __half* Af, const __half* Wf, int K,
    int bm, int bn, int k0, uint32_t sstage, int tid)
{
#pragma unroll
    for (int i = 0; i < 4; i++) {
        int idx = tid + 256 * i;
        int buf = idx >> 9;
        int rem = idx & 511;
        int r = rem >> 2, cg = rem & 3;
        const __half* src = buf ? (Wf + (size_t)(bn + r) * K + k0 + cg * 8)
                                : (Af + (size_t)(bm + r) * K + k0 + cg * 8);
        CP_ASYNC16(sstage + (uint32_t)(buf * GBUF + r * (GP * 2) + cg * 16),
                   (const char*)src);
    }
}

__global__ void __launch_bounds__(256, 1) gemm_f16_kernel(
    const __half* __restrict__ Af, const __half* __restrict__ Wf,
    const float* __restrict__ res, float* __restrict__ Cf,
    __half* __restrict__ Ch,
    int Mtot, int Ntot, int K, int mode)
{
    extern __shared__ char gsm[];
    uint32_t sb = smem_u32(gsm);
    int tid = threadIdx.x;
    int lane = tid & 31, w = tid >> 5;
    int wm = (w & 3) * 32, wn = (w >> 2) * 64;
    int bm = blockIdx.y * 128, bn = blockIdx.x * 128;

    float acc[2][8][4];
#pragma unroll
    for (int mt = 0; mt < 2; mt++)
#pragma unroll
        for (int nt = 0; nt < 8; nt++)
#pragma unroll
            for (int e = 0; e < 4; e++) acc[mt][nt][e] = 0.f;

    int nc = K / 32;
    load_chunk_g(Af, Wf, K, bm, bn, 0, sb, tid);               CP_COMMIT();
    load_chunk_g(Af, Wf, K, bm, bn, 32, sb + GSTAGE, tid);     CP_COMMIT();
    load_chunk_g(Af, Wf, K, bm, bn, 64, sb + 2 * GSTAGE, tid); CP_COMMIT();

    for (int c = 0; c < nc; c++) {
        if (c + 3 <= nc)      { CP_WAIT(2); }
        else if (c + 2 <= nc) { CP_WAIT(1); }
        else                  { CP_WAIT(0); }
        __syncthreads();
        if (c + 3 < nc) {
            load_chunk_g(Af, Wf, K, bm, bn, (c + 3) * 32,
                         sb + (uint32_t)(((c + 3) & 3) * GSTAGE), tid);
            CP_COMMIT();
        }
        uint32_t st = sb + (uint32_t)((c & 3) * GSTAGE);
#pragma unroll
        for (int ks = 0; ks < 2; ks++) {
            int k0 = ks * 16;
            uint32_t a[2][4], bh[4][4];
#pragma unroll
            for (int mt = 0; mt < 2; mt++) {
                uint32_t row = (uint32_t)(wm + mt * 16 + (lane & 15));
                uint32_t col = (uint32_t)(k0 + ((lane >> 4) << 3));
                ldsm_x4(a[mt], st + row * (GP * 2) + col * 2);
            }
#pragma unroll
            for (int g = 0; g < 4; g++) {
                uint32_t grp = (uint32_t)(lane >> 3);
                uint32_t row = (uint32_t)(wn + g * 16) + ((grp >> 1) << 3) + (uint32_t)(lane & 7);
                uint32_t col = (uint32_t)k0 + ((grp & 1) << 3);
                ldsm_x4(bh[g], st + GBUF + row * (GP * 2) + col * 2);
            }
#pragma unroll
            for (int mt = 0; mt < 2; mt++)
#pragma unroll
                for (int nt = 0; nt < 8; nt++)
                    mma_f16h(acc[mt][nt], a[mt],
                             bh[nt >> 1][(nt & 1) * 2], bh[nt >> 1][(nt & 1) * 2 + 1]);
        }
    }

    // epilogue
#pragma unroll
    for (int mt = 0; mt < 2; mt++)
#pragma unroll
        for (int nt = 0; nt < 8; nt++) {
            int m0 = bm + wm + mt * 16 + (lane >> 2);
            int n  = bn + wn + nt * 8 + ((lane & 3) << 1);
            if (mode == 2) {
                // acc pair = (p1, p2) at interleaved cols; output col = n/2 of N/2-wide buffer
                int no2 = Ntot >> 1;
                Ch[(size_t)m0 * no2 + (n >> 1)] =
                    __float2half(acc[mt][nt][0] * gelu_t(acc[mt][nt][1]));
                Ch[(size_t)(m0 + 8) * no2 + (n >> 1)] =
                    __float2half(acc[mt][nt][2] * gelu_t(acc[mt][nt][3]));
            } else if (mode == 1) {
                size_t i0 = (size_t)m0 * Ntot + n;
                size_t i1 = (size_t)(m0 + 8) * Ntot + n;
                *(__half2*)(Ch + i0) = __floats2half2_rn(acc[mt][nt][0], acc[mt][nt][1]);
                *(__half2*)(Ch + i1) = __floats2half2_rn(acc[mt][nt][2], acc[mt][nt][3]);
            } else {
                size_t i0 = (size_t)m0 * Ntot + n;
                size_t i1 = (size_t)(m0 + 8) * Ntot + n;
                float2 v0 = make_float2(acc[mt][nt][0], acc[mt][nt][1]);
                float2 v1 = make_float2(acc[mt][nt][2], acc[mt][nt][3]);
                if (res) {
                    float2 r0 = *(const float2*)(res + i0);
                    float2 r1 = *(const float2*)(res + i1);
                    v0.x += r0.x; v0.y += r0.y;
                    v1.x += r1.x; v1.y += r1.y;
                }
                *(float2*)(Cf + i0) = v0;
                *(float2*)(Cf + i1) = v1;
            }
        }
}

// ================= tensor-core flash attention (f16) + fused pos_bias output =================
#define QP 72
#define PP 136
#define SQ_OFF 0
#define SKV0 9216
#define SKV1 27648
#define SKVSZ 9216
#define SP_OFF 46080
#define SP_END (46080 + 128 * PP)
#define BIAS_BYTE (SP_END * 2)
#define MW_BYTE (BIAS_BYTE + 4096 * 4)
#define ATT_SMEM (MW_BYTE + 1024 * 4)

__global__ void __launch_bounds__(256, 1) attn_tc_kernel(
    const __half* __restrict__ qkv, const uint32_t* __restrict__ mbits,
    const float* __restrict__ relb, const int* __restrict__ btab,
    __half* __restrict__ of, float* __restrict__ pbias)
{
    extern __shared__ char asmem[];
    uint32_t sb = smem_u32(asmem);
    float* biasAll = (float*)(asmem + BIAS_BYTE);
    uint32_t* mwp  = (uint32_t*)(asmem + MW_BYTE);

    int qt = blockIdx.x, h = blockIdx.y, b = blockIdx.z;
    int tid = threadIdx.x;
    int lane = tid & 31, w = tid >> 5;
    int i0 = qt * 128;

    for (int u = tid; u < 4095; u += 256)
        biasAll[u] = relb[btab[u] * HH + h];

    const __half* qf = qkv + h * 64;
    const __half* kf = qkv + 1024 + h * 64;
    const __half* vf = qkv + 2048 + h * 64;

    // prologue: Q tile + KV tile 0 + mask 0
    size_t qbase = (size_t)(b * TT + i0) * QS;
#pragma unroll
    for (int i = 0; i < 4; i++) {
        int c = tid + 256 * i;
        int r = c >> 3, cg = c & 7;
        CP_ASYNC16(sb + (uint32_t)((SQ_OFF + r * QP + cg * 8) * 2),
                   (const char*)(qf + qbase + (size_t)r * QS + cg * 8));
    }
    size_t kvbase0 = (size_t)(b * TT) * QS;
#pragma unroll
    for (int i = 0; i < 8; i++) {
        int c = tid + 256 * i;
        int buf = c >> 10, r = (c >> 3) & 127, cg = c & 7;
        const __half* srcp = (buf ? vf : kf) + kvbase0 + (size_t)r * QS + cg * 8;
        CP_ASYNC16(sb + (uint32_t)((SKV0 + buf * SKVSZ + r * QP + cg * 8) * 2),
                   (const char*)srcp);
    }
    CP_COMMIT();
#pragma unroll
    for (int i = 0; i < 2; i++) {
        int idx = tid + 256 * i;
        int r = idx >> 2, ws = idx & 3;
        mwp[idx] = mbits[(size_t)(b * TT + i0 + r) * 64 + ws];
    }
    CP_WAIT(0);
    __syncthreads();

    uint32_t aq[4][4];
#pragma unroll
    for (int ks = 0; ks < 4; ks++) {
        uint32_t row = (uint32_t)(w * 16 + (lane & 15));
        uint32_t col = (uint32_t)(ks * 16 + ((lane >> 4) << 3));
        ldsm_x4(aq[ks], sb + (SQ_OFF + row * QP + col) * 2);
    }

    float o[8][4];
#pragma unroll
    for (int nt = 0; nt < 8; nt++)
#pragma unroll
        for (int e = 0; e < 4; e++) o[nt][e] = 0.f;
    float m0p = -1e30f, m1p = -1e30f, l0 = 0.f, l1 = 0.f;
    int rl0 = w * 16 + (lane >> 2);

    const int NT = TT / 128;
    for (int kt = 0; kt < NT; kt++) {
        CP_WAIT(0);
        __syncthreads();

        // prefetch tile kt+1
        if (kt + 1 < NT) {
            size_t kvb = (size_t)(b * TT + (kt + 1) * 128) * QS;
            uint32_t dstb = (uint32_t)(((kt + 1) & 1) ? SKV1 : SKV0);
#pragma unroll
            for (int i = 0; i < 8; i++) {
                int c = tid + 256 * i;
                int buf = c >> 10, r = (c >> 3) & 127, cg = c & 7;
                const __half* srcp = (buf ? vf : kf) + kvb + (size_t)r * QS + cg * 8;
                CP_ASYNC16(sb + (uint32_t)((dstb + buf * SKVSZ + r * QP + cg * 8) * 2),
                           (const char*)srcp);
            }
            CP_COMMIT();
#pragma unroll
            for (int i = 0; i < 2; i++) {
                int idx = tid + 256 * i;
                int r = idx >> 2, ws = idx & 3;
                mwp[((kt + 1) & 1) * 512 + idx] =
                    mbits[(size_t)(b * TT + i0 + r) * 64 + ((kt + 1) * 4) + ws];
            }
        }

        // ---- fused pos_bias output: this CTA writes 64 rows (split by b), 4 per iter ----
        {
            int br = i0 + (b ? 64 : 0) + kt * 4 + (tid >> 6);     // 4 rows/iter
            const float* srcw = biasAll + (2047 - br);
            float* dst = pbias + ((size_t)h * TT + br) * TT;
#pragma unroll
            for (int q4 = 0; q4 < 8; q4++) {
                int j = q4 * 256 + (tid & 63) * 4;
                float4 v = make_float4(srcw[j], srcw[j + 1], srcw[j + 2], srcw[j + 3]);
                *(float4*)(dst + j) = v;
            }
        }

        uint32_t skv = (uint32_t)((kt & 1) ? SKV1 : SKV0);
        int j0 = kt * 128;

        // S = Q K^T
        float s[16][4];
#pragma unroll
        for (int t = 0; t < 16; t++)
#pragma unroll
            for (int e = 0; e < 4; e++) s[t][e] = 0.f;
#pragma unroll
        for (int ks = 0; ks < 4; ks++) {
#pragma unroll
            for (int g = 0; g < 8; g++) {
                uint32_t grp = (uint32_t)(lane >> 3);
                uint32_t row = (uint32_t)(g * 16) + ((grp >> 1) << 3) + (uint32_t)(lane & 7);
                uint32_t col = (uint32_t)(ks * 16) + ((grp & 1) << 3);
                uint32_t bk[4];
                ldsm_x4(bk, sb + (skv + row * QP + col) * 2);
                mma_f16h(s[g * 2 + 0], aq[ks], bk[0], bk[1]);
                mma_f16h(s[g * 2 + 1], aq[ks], bk[2], bk[3]);
            }
        }

        // bias + mask
        int ub = 2047 + j0 - i0;
        const uint32_t* mw = mwp + (kt & 1) * 512;
        uint32_t mA[4], mB[4];
#pragma unroll
        for (int k2 = 0; k2 < 4; k2++) {
            mA[k2] = mw[rl0 * 4 + k2];
            mB[k2] = mw[(rl0 + 8) * 4 + k2];
        }
#pragma unroll
        for (int t = 0; t < 16; t++) {
            int cjb = t * 8 + ((lane & 3) << 1);
#pragma unroll
            for (int e = 0; e < 4; e++) {
                int cj = cjb + (e & 1);
                int rl = (e < 2) ? rl0 : rl0 + 8;
                float val = s[t][e] + biasAll[ub + cj - rl];
                uint32_t mv = ((e < 2) ? mA : mB)[cj >> 5];
                s[t][e] = ((mv >> (cj & 31)) & 1u) ? val : -1e9f;
            }
        }

        // online softmax (warp-local rows)
        float mx0 = -1e30f, mx1 = -1e30f;
#pragma unroll
        for (int t = 0; t < 16; t++) {
            mx0 = fmaxf(mx0, fmaxf(s[t][0], s[t][1]));
            mx1 = fmaxf(mx1, fmaxf(s[t][2], s[t][3]));
        }
        mx0 = fmaxf(mx0, __shfl_xor_sync(0xffffffffu, mx0, 1));
        mx0 = fmaxf(mx0, __shfl_xor_sync(0xffffffffu, mx0, 2));
        mx1 = fmaxf(mx1, __shfl_xor_sync(0xffffffffu, mx1, 1));
        mx1 = fmaxf(mx1, __shfl_xor_sync(0xffffffffu, mx1, 2));
        float mn0 = fmaxf(m0p, mx0), mn1 = fmaxf(m1p, mx1);
        float corr0 = __expf(m0p - mn0), corr1 = __expf(m1p - mn1);
        float sm0 = 0.f, sm1 = 0.f;
#pragma unroll
        for (int t = 0; t < 16; t++) {
            float p0 = __expf(s[t][0] - mn0);
            float p1 = __expf(s[t][1] - mn0);
            float p2 = __expf(s[t][2] - mn1);
            float p3 = __expf(s[t][3] - mn1);
            sm0 += p0 + p1; sm1 += p2 + p3;
            int cb = t * 8 + ((lane & 3) << 1);
            *(__half2*)(asmem + (SP_OFF + rl0 * PP + cb) * 2)       = __floats2half2_rn(p0, p1);
            *(__half2*)(asmem + (SP_OFF + (rl0 + 8) * PP + cb) * 2) = __floats2half2_rn(p2, p3);
        }
        sm0 += __shfl_xor_sync(0xffffffffu, sm0, 1);
        sm0 += __shfl_xor_sync(0xffffffffu, sm0, 2);
        sm1 += __shfl_xor_sync(0xffffffffu, sm1, 1);
        sm1 += __shfl_xor_sync(0xffffffffu, sm1, 2);
        l0 = l0 * corr0 + sm0;
        l1 = l1 * corr1 + sm1;
        m0p = mn0; m1p = mn1;
#pragma unroll
        for (int nt = 0; nt < 8; nt++) {
            o[nt][0] *= corr0; o[nt][1] *= corr0;
            o[nt][2] *= corr1; o[nt][3] *= corr1;
        }
        __syncwarp();

        // O += P V
#pragma unroll
        for (int ks = 0; ks < 8; ks++) {
            uint32_t ap[4];
            {
                uint32_t row = (uint32_t)(w * 16 + (lane & 15));
                uint32_t col = (uint32_t)(ks * 16 + ((lane >> 4) << 3));
                ldsm_x4(ap, sb + (SP_OFF + row * PP + col) * 2);
            }
#pragma unroll
            for (int g = 0; g < 4; g++) {
                uint32_t row = (uint32_t)(ks * 16 + (lane & 15));
                uint32_t col = (uint32_t)(g * 16 + ((lane >> 4) << 3));
                uint32_t bv[4];
                ldsm_x4_t(bv, sb + (skv + SKVSZ + row * QP + col) * 2);
                mma_f16h(o[g * 2 + 0], ap, bv[0], bv[1]);
                mma_f16h(o[g * 2 + 1], ap, bv[2], bv[3]);
            }
        }
    }

    // epilogue
    float il0 = 1.f / l0, il1 = 1.f / l1;
    size_t r0g = ((size_t)b * TT + i0 + rl0) * DD + h * 64;
    size_t r1g = r0g + (size_t)8 * DD;
#pragma unroll
    for (int nt = 0; nt < 8; nt++) {
        int col = nt * 8 + ((lane & 3) << 1);
        *(__half2*)(of + r0g + col) = __floats2half2_rn(o[nt][0] * il0, o[nt][1] * il0);
        *(__half2*)(of + r1g + col) = __floats2half2_rn(o[nt][2] * il1, o[nt][3] * il1);
    }
}

// ---------------- launch ----------------
extern "C" void kernel_launch(void* const* d_in, const int* in_sizes, int n_in,
                              void* d_out, int out_size) {
    const float* x     = (const float*)d_in[0];
    const int*   xmask = (const int*)d_in[1];
    const float* n1w   = (const float*)d_in[3];
    const float* n3w   = (const float*)d_in[4];
    const float* wqW   = (const float*)d_in[5];
    const float* wqA   = (const float*)d_in[6];
    const float* wqB   = (const float*)d_in[7];
    const float* wkW   = (const float*)d_in[8];
    const float* wvW   = (const float*)d_in[9];
    const float* wvA   = (const float*)d_in[10];
    const float* wvB   = (const float*)d_in[11];
    const float* fcW   = (const float*)d_in[12];
    const float* fcA   = (const float*)d_in[13];
    const float* fcB   = (const float*)d_in[14];
    const float* relb  = (const float*)d_in[15];
    const float* w1W   = (const float*)d_in[16];
    const float* w1A   = (const float*)d_in[17];
    const float* w1B   = (const float*)d_in[18];
    const float* w2W   = (const float*)d_in[19];
    const float* w2A   = (const float*)d_in[20];
    const float* w2B   = (const float*)d_in[21];

    float* scratch = nullptr;
    int* btab = nullptr;
    uint32_t* mbits = nullptr;
    cudaGetSymbolAddress((void**)&scratch, g_scratch);
    cudaGetSymbolAddress((void**)&btab, g_btab);
    cudaGetSymbolAddress((void**)&mbits, g_mbits);

    __half* qkvh = (__half*)(scratch + OFF_QKV);
    __half* ofp  = (__half*)(scratch + OFF_OF);
    __half* yf   = (__half*)(scratch + OFF_YF);
    __half* y3f  = (__half*)(scratch + OFF_Y3F);
    __half* ygf  = (__half*)(scratch + OFF_YGF);
    float*  x1   = scratch + OFF_X1;
    __half* wqkv = (__half*)(scratch + OFF_WQKV);
    __half* wfc  = (__half*)(scratch + OFF_WFC);
    __half* w1   = (__half*)(scratch + OFF_W1);
    __half* w2   = (__half*)(scratch + OFF_W2);

    float* out_x    = (float*)d_out;
    float* out_bias = out_x + (size_t)MM * DD;

    cudaFuncSetAttribute(gemm_f16_kernel, cudaFuncAttributeMaxDynamicSharedMemorySize, GEMM_SMEM);
    cudaFuncSetAttribute(attn_tc_kernel, cudaFuncAttributeMaxDynamicSharedMemorySize, ATT_SMEM);

    // 1) tables + mask bits
    bucket_kernel<<<(4095 + 255) / 256, 256>>>(btab);
    maskbits_kernel<<<(BB * TT * 64) / 256, 256>>>(xmask, mbits);

    // 2) weights -> f16 (q scaled 1/8; w1 row-interleaved for fused geglu)
    merge_f16_kernel<<<(DD * DD) / 256, 256>>>(wqW, wqA, wqB, wqkv, DD, DD, 0.125f);
    convert_f16_kernel<<<(DD * DD) / 256, 256>>>(wkW, wqkv + (size_t)DD * DD, DD * DD);
    merge_f16_kernel<<<(DD * DD) / 256, 256>>>(wvW, wvA, wvB, wqkv + (size_t)2 * DD * DD, DD, DD, 1.0f);
    merge_f16_kernel<<<(DD * DD) / 256, 256>>>(fcW, fcA, fcB, wfc, DD, DD, 1.0f);
    merge_w1i_kernel<<<(4 * DD * DD) / 256, 256>>>(w1W, w1A, w1B, w1);
    merge_f16_kernel<<<(2 * DD * DD) / 256, 256>>>(w2W, w2A, w2B, w2, DD, 2 * DD, 1.0f);

    // 3) attention block (pos_bias written inside attention kernel)
    rmsnorm_f16_kernel<<<MM, 256>>>(x, n1w, yf);
    {
        dim3 g(QS / 128, MM / 128);
        gemm_f16_kernel<<<g, 256, GEMM_SMEM>>>(yf, wqkv, nullptr, nullptr, qkvh, MM, QS, DD, 1);
    }
    {
        dim3 g(TT / 128, HH, BB);
        attn_tc_kernel<<<g, 256, ATT_SMEM>>>(qkvh, mbits, relb, btab, ofp, out_bias);
    }
    {
        dim3 g(DD / 128, MM / 128);
        gemm_f16_kernel<<<g, 256, GEMM_SMEM>>>(ofp, wfc, x, x1, nullptr, MM, DD, DD, 0);
    }

    // 4) GEGLU MLP (geglu fused into w1 epilogue)
    rmsnorm_f16_kernel<<<MM, 256>>>(x1, n3w, y3f);
    {
        dim3 g(4 * DD / 128, MM / 128);
        gemm_f16_kernel<<<g, 256, GEMM_SMEM>>>(y3f, w1, nullptr, nullptr, ygf, MM, 4 * DD, DD, 2);
    }
    {
        dim3 g(DD / 128, MM / 128);
        gemm_f16_kernel<<<g, 256, GEMM_SMEM>>>(ygf, w2, x1, out_x, nullptr, MM, DD, 2 * DD, 0);
    }
}